// round 4
// baseline (speedup 1.0000x reference)
#include <cuda_runtime.h>
#include <math.h>

// Problem constants
#define D_     512
#define TD_    1024
#define NSYM_  512
#define NCON_  64
#define NV_    256
#define NPOS_  16384
#define DEPTH_ 6
#define EPS_   1e-8f
#define CC_    0.25f
#define SCALE_ 0.04419417382415922f   // 512^-0.5

// ---------------------------------------------------------------------------
// Static device scratch
// ---------------------------------------------------------------------------
__device__ float g_W2[TD_*TD_];         // interleaved cell weight [1024,1024]
__device__ float g_embed[NV_*TD_];
__device__ float g_z0[NV_*TD_];
__device__ float g_cellTab[NSYM_*TD_];
__device__ float g_C2[NSYM_*TD_];
__device__ float g_C3[NSYM_*TD_];
__device__ float g_lookOut[NSYM_*NV_];
__device__ float g_Ksym[NSYM_*D_];
__device__ float g_Vsym[NSYM_*TD_];
__device__ float g_Qtab[NSYM_*D_];
__device__ float g_QK[NSYM_*NSYM_];
__device__ float g_CS[NSYM_*NSYM_];
__device__ float g_VS[NSYM_*NSYM_];
__device__ float g_Z0S[NV_*NSYM_];
__device__ float g_sym2[NSYM_];
__device__ float g_conDist[NSYM_];
__device__ int   g_hist[NV_];
__device__ int   g_fin[NV_];
__device__ float g_symLv[NV_];
__device__ float g_conLv[NV_];

// ---------------------------------------------------------------------------
// f32x2 packed FMA helpers
// ---------------------------------------------------------------------------
union UF2 { unsigned long long u; float2 f; };

__device__ __forceinline__ void ffma2(unsigned long long &acc,
                                      unsigned long long a, unsigned long long b)
{
    asm("fma.rn.f32x2 %0, %1, %2, %0;" : "+l"(acc) : "l"(a), "l"(b));
}
__device__ __forceinline__ unsigned long long dup2(float v)
{
    UF2 u; u.f.x = v; u.f.y = v; return u.u;
}

// ---------------------------------------------------------------------------
// 64x64 GEMM tile, 128 threads, f32x2 micro-kernel, double-buffered.
// C[M,N] = A[M,K] @ B[N,K]^T (+bias).  CELL=1: B is W2int; epilogue computes
// the complex cell nonlinearity on adjacent (lr,li) column pairs and writes
// to Zout[M,1024] at columns p and p+512.
// smem: As[2][16][64] (transposed) + Bs[2][16][128] (value-duplicated pairs)
// ---------------------------------------------------------------------------
#define GEMM_SMEM (2*16*64 + 2*16*128)   // 6144 floats = 24 KB

template<int CELL>
__device__ __forceinline__ void dev_gemm64(
    const float* __restrict__ A, const float* __restrict__ B,
    const float* __restrict__ bias, float* __restrict__ C,
    int N, int K, int bx, int by, float* smemBase)
{
    float (*As)[16][64]  = (float (*)[16][64])smemBase;
    float (*Bs)[16][128] = (float (*)[16][128])(smemBase + 2*16*64);

    const int tid = threadIdx.x;
    const int tx = tid & 15, ty = tid >> 4;         // 16 x 8
    const int m0 = by * 64, n0 = bx * 64;
    const int lrow = tid & 63;                      // 0..63
    const int lk   = tid >> 6;                      // 0..1

    const float* gA = A + (size_t)(m0 + lrow) * K + lk * 8;
    const float* gB = B + (size_t)(n0 + lrow) * K + lk * 8;

    UF2 acc[4][4];
#pragma unroll
    for (int i = 0; i < 4; i++)
#pragma unroll
        for (int j = 0; j < 4; j++) acc[i][j].u = 0ull;

    const int nk = K >> 4;

    float4 a0v = *(const float4*)(gA);
    float4 a1v = *(const float4*)(gA + 4);
    float4 b0v = *(const float4*)(gB);
    float4 b1v = *(const float4*)(gB + 4);
    {
        const int kb = lk * 8;
#pragma unroll
        for (int c = 0; c < 4; c++) {
            As[0][kb + c][lrow]     = ((float*)&a0v)[c];
            As[0][kb + 4 + c][lrow] = ((float*)&a1v)[c];
        }
#pragma unroll
        for (int c = 0; c < 4; c++) {
            *(unsigned long long*)&Bs[0][kb + c][2*lrow]     = dup2(((float*)&b0v)[c]);
            *(unsigned long long*)&Bs[0][kb + 4 + c][2*lrow] = dup2(((float*)&b1v)[c]);
        }
    }
    __syncthreads();

    for (int t = 0; t < nk; t++) {
        const int cur = t & 1;
        if (t + 1 < nk) {
            const float* pa = gA + (t + 1) * 16;
            const float* pb = gB + (t + 1) * 16;
            a0v = *(const float4*)(pa);
            a1v = *(const float4*)(pa + 4);
            b0v = *(const float4*)(pb);
            b1v = *(const float4*)(pb + 4);
        }
#pragma unroll
        for (int kk = 0; kk < 16; kk++) {
            const float* Ak = &As[cur][kk][ty * 8];
            const float* Bk = &Bs[cur][kk][tx * 4];
            unsigned long long ap0 = *(const unsigned long long*)(Ak + 0);
            unsigned long long ap1 = *(const unsigned long long*)(Ak + 2);
            unsigned long long ap2 = *(const unsigned long long*)(Ak + 4);
            unsigned long long ap3 = *(const unsigned long long*)(Ak + 6);
            unsigned long long bp0 = *(const unsigned long long*)(Bk + 0);
            unsigned long long bp1 = *(const unsigned long long*)(Bk + 2);
            unsigned long long bp2 = *(const unsigned long long*)(Bk + 64);
            unsigned long long bp3 = *(const unsigned long long*)(Bk + 66);
            ffma2(acc[0][0].u, ap0, bp0); ffma2(acc[0][1].u, ap0, bp1);
            ffma2(acc[0][2].u, ap0, bp2); ffma2(acc[0][3].u, ap0, bp3);
            ffma2(acc[1][0].u, ap1, bp0); ffma2(acc[1][1].u, ap1, bp1);
            ffma2(acc[1][2].u, ap1, bp2); ffma2(acc[1][3].u, ap1, bp3);
            ffma2(acc[2][0].u, ap2, bp0); ffma2(acc[2][1].u, ap2, bp1);
            ffma2(acc[2][2].u, ap2, bp2); ffma2(acc[2][3].u, ap2, bp3);
            ffma2(acc[3][0].u, ap3, bp0); ffma2(acc[3][1].u, ap3, bp1);
            ffma2(acc[3][2].u, ap3, bp2); ffma2(acc[3][3].u, ap3, bp3);
        }
        if (t + 1 < nk) {
            __syncthreads();
            const int nb = cur ^ 1, kb = lk * 8;
#pragma unroll
            for (int c = 0; c < 4; c++) {
                As[nb][kb + c][lrow]     = ((float*)&a0v)[c];
                As[nb][kb + 4 + c][lrow] = ((float*)&a1v)[c];
            }
#pragma unroll
            for (int c = 0; c < 4; c++) {
                *(unsigned long long*)&Bs[nb][kb + c][2*lrow]     = dup2(((float*)&b0v)[c]);
                *(unsigned long long*)&Bs[nb][kb + 4 + c][2*lrow] = dup2(((float*)&b1v)[c]);
            }
            __syncthreads();
        }
    }

    if (!CELL) {
        float2 b01 = make_float2(0.f, 0.f), b23 = make_float2(0.f, 0.f);
        if (bias) {
            b01 = *(const float2*)(bias + n0 + 2*tx);
            b23 = *(const float2*)(bias + n0 + 2*tx + 32);
        }
#pragma unroll
        for (int mp = 0; mp < 4; mp++) {
            int r0 = m0 + ty*8 + 2*mp;
            float2 lo01 = make_float2(acc[mp][0].f.x + b01.x, acc[mp][1].f.x + b01.y);
            float2 lo23 = make_float2(acc[mp][2].f.x + b23.x, acc[mp][3].f.x + b23.y);
            float2 hi01 = make_float2(acc[mp][0].f.y + b01.x, acc[mp][1].f.y + b01.y);
            float2 hi23 = make_float2(acc[mp][2].f.y + b23.x, acc[mp][3].f.y + b23.y);
            *(float2*)(C + (size_t)r0*N + n0 + 2*tx)          = lo01;
            *(float2*)(C + (size_t)r0*N + n0 + 2*tx + 32)     = lo23;
            *(float2*)(C + (size_t)(r0+1)*N + n0 + 2*tx)      = hi01;
            *(float2*)(C + (size_t)(r0+1)*N + n0 + 2*tx + 32) = hi23;
        }
    } else {
        const int p0 = (n0 >> 1) + tx;   // cols 2tx,2tx+1 -> pair p0
        const int p1 = p0 + 16;          // cols 2tx+32,2tx+33 -> pair p1
#pragma unroll
        for (int mp = 0; mp < 4; mp++) {
            int r0 = m0 + ty*8 + 2*mp;
            {
                float lr = acc[mp][0].f.x, li = acc[mp][1].f.x;
                float mm = sqrtf(lr*lr + li*li + EPS_);
                C[(size_t)r0*TD_ + p0]      = tanhf(lr / (1.f + mm));
                C[(size_t)r0*TD_ + p0 + D_] = tanhf(li / (1.f + mm));
            }
            {
                float lr = acc[mp][0].f.y, li = acc[mp][1].f.y;
                float mm = sqrtf(lr*lr + li*li + EPS_);
                C[(size_t)(r0+1)*TD_ + p0]      = tanhf(lr / (1.f + mm));
                C[(size_t)(r0+1)*TD_ + p0 + D_] = tanhf(li / (1.f + mm));
            }
            {
                float lr = acc[mp][2].f.x, li = acc[mp][3].f.x;
                float mm = sqrtf(lr*lr + li*li + EPS_);
                C[(size_t)r0*TD_ + p1]      = tanhf(lr / (1.f + mm));
                C[(size_t)r0*TD_ + p1 + D_] = tanhf(li / (1.f + mm));
            }
            {
                float lr = acc[mp][2].f.y, li = acc[mp][3].f.y;
                float mm = sqrtf(lr*lr + li*li + EPS_);
                C[(size_t)(r0+1)*TD_ + p1]      = tanhf(lr / (1.f + mm));
                C[(size_t)(r0+1)*TD_ + p1 + D_] = tanhf(li / (1.f + mm));
            }
        }
    }
}

// ---------------------------------------------------------------------------
// Stage 0 (prep, 417 blocks x 256): embed | W2int build | sym2 | conDist | hist
// ---------------------------------------------------------------------------
__global__ __launch_bounds__(256)
void s0_kernel(const float* __restrict__ mag, const float* __restrict__ phase,
               const float* __restrict__ Wr,  const float* __restrict__ Wi,
               const float* __restrict__ sym, const float* __restrict__ con,
               const int* __restrict__ x)
{
    const int b = blockIdx.x, tid = threadIdx.x;

    if (b < 32) {                              // embed: 8 vocab rows per block
        int base = b * 8;
#pragma unroll
        for (int vv = 0; vv < 8; vv++) {
            int v = base + vv;
            for (int i = tid; i < D_; i += 256) {
                float r = mag[v*D_ + i];
                float t = phase[v*D_ + i];
                g_embed[v*TD_ + i]      = r * cosf(t);
                g_embed[v*TD_ + D_ + i] = r * sinf(t);
            }
        }
    } else if (b < 288) {                      // W2int: 4 rows per block
        int idx = b - 32;
        int k = tid * 4;
#pragma unroll
        for (int rr = 0; rr < 4; rr++) {
            int r = idx*4 + rr;
            int n = r >> 1;
            int odd = r & 1;
            float4 v;
            if (k < D_) {
                v = *(const float4*)((odd ? Wi : Wr) + (size_t)n*D_ + k);
            } else {
                int k2 = k - D_;
                if (odd) v = *(const float4*)(Wr + (size_t)n*D_ + k2);
                else {
                    v = *(const float4*)(Wi + (size_t)n*D_ + k2);
                    v.x = -v.x; v.y = -v.y; v.z = -v.z; v.w = -v.w;
                }
            }
            *(float4*)(g_W2 + (size_t)r*TD_ + k) = v;
        }
    } else if (b < 352) {                      // sym2: 8 rows per block
        int local = b - 288;
        int w = tid >> 5, lane = tid & 31;
        int row = local*8 + w;
        float s = 0.f;
        const float* src = sym + (size_t)row*TD_;
        for (int i = lane; i < TD_; i += 32) { float v = src[i]; s += v*v; }
#pragma unroll
        for (int o = 16; o > 0; o >>= 1) s += __shfl_down_sync(0xffffffffu, s, o);
        if (lane == 0) g_sym2[row] = s;
    } else if (b < 416) {                      // conDist: 8 sym rows per block
        int local = b - 352;
        int w = tid >> 5, lane = tid & 31;
        int row = local*8 + w;
        float sv[32];
#pragma unroll
        for (int c = 0; c < 32; c++) sv[c] = sym[(size_t)row*TD_ + c*32 + lane];
        float best = 1e30f;
        for (int j = 0; j < NCON_; j++) {
            const float* cj = con + (size_t)j*TD_;
            float s = 0.f;
#pragma unroll
            for (int c = 0; c < 32; c++) { float d = sv[c] - cj[c*32 + lane]; s += d*d; }
#pragma unroll
            for (int o = 16; o > 0; o >>= 1) s += __shfl_xor_sync(0xffffffffu, s, o);
            best = fminf(best, s);
        }
        if (lane == 0) g_conDist[row] = best;
    } else {                                   // histogram of x
        __shared__ int hist[NV_];
        hist[tid] = 0; __syncthreads();
        for (int i = tid; i < NPOS_; i += 256) atomicAdd(&hist[x[i]], 1);
        __syncthreads();
        g_hist[tid] = hist[tid];
    }
}

// ---------------------------------------------------------------------------
// Stage 1 (256 x 128): cellTab (128) | z0 (64) | Ksym (64)
// ---------------------------------------------------------------------------
__global__ __launch_bounds__(128)
void s1_kernel(const float* __restrict__ sym,
               const float* __restrict__ kw, const float* __restrict__ kb)
{
    __shared__ float sm[GEMM_SMEM];
    const int b = blockIdx.x;
    if (b < 128) {
        dev_gemm64<1>(sym, g_W2, nullptr, g_cellTab, TD_, TD_, b & 15, b >> 4, sm);
    } else if (b < 192) {
        int t = b - 128;
        dev_gemm64<1>(g_embed, g_W2, nullptr, g_z0, TD_, TD_, t & 15, t >> 4, sm);
    } else {
        int t = b - 192;
        dev_gemm64<0>(sym, kw, kb, g_Ksym, D_, TD_, t & 7, t >> 3, sm);
    }
}

// ---------------------------------------------------------------------------
// Stage 2 (320 x 128): Vsym (128) | C2 (128) | Qtab (64)
// ---------------------------------------------------------------------------
__global__ __launch_bounds__(128)
void s2_kernel(const float* __restrict__ sym,
               const float* __restrict__ vw, const float* __restrict__ vb,
               const float* __restrict__ qw, const float* __restrict__ qb)
{
    __shared__ float sm[GEMM_SMEM];
    const int b = blockIdx.x;
    if (b < 128) {
        dev_gemm64<0>(sym, vw, vb, g_Vsym, TD_, TD_, b & 15, b >> 4, sm);
    } else if (b < 256) {
        int t = b - 128;
        dev_gemm64<1>(g_cellTab, g_W2, nullptr, g_C2, TD_, TD_, t & 15, t >> 4, sm);
    } else {
        int t = b - 256;
        dev_gemm64<0>(g_cellTab, qw, qb, g_Qtab, D_, TD_, t & 7, t >> 3, sm);
    }
}

// ---------------------------------------------------------------------------
// Stage 3 (352 x 128): CS (64) | VS (64) | Z0S (32) | QK (64) | C3 (128)
// ---------------------------------------------------------------------------
__global__ __launch_bounds__(128)
void s3_kernel(const float* __restrict__ sym)
{
    __shared__ float sm[GEMM_SMEM];
    const int b = blockIdx.x;
    if (b < 64) {
        dev_gemm64<0>(g_cellTab, sym, nullptr, g_CS, NSYM_, TD_, b & 7, b >> 3, sm);
    } else if (b < 128) {
        int t = b - 64;
        dev_gemm64<0>(g_Vsym, sym, nullptr, g_VS, NSYM_, TD_, t & 7, t >> 3, sm);
    } else if (b < 160) {
        int t = b - 128;
        dev_gemm64<0>(g_z0, sym, nullptr, g_Z0S, NSYM_, TD_, t & 7, t >> 3, sm);
    } else if (b < 224) {
        int t = b - 160;
        dev_gemm64<0>(g_Qtab, g_Ksym, nullptr, g_QK, NSYM_, D_, t & 7, t >> 3, sm);
    } else {
        int t = b - 224;
        dev_gemm64<1>(g_C2, g_W2, nullptr, g_C3, TD_, TD_, t & 15, t >> 4, sm);
    }
}

// ---------------------------------------------------------------------------
// Stage 4a (32 x 128): lookOut = C3 @ dec_w^T + dec_b   [512,256]
// ---------------------------------------------------------------------------
__global__ __launch_bounds__(128)
void s4a_kernel(const float* __restrict__ dec_w, const float* __restrict__ dec_b)
{
    __shared__ float sm[GEMM_SMEM];
    const int b = blockIdx.x;
    dev_gemm64<0>(g_C3, dec_w, dec_b, g_lookOut, NV_, TD_, b & 3, b >> 2, sm);
}

// ---------------------------------------------------------------------------
// Stage 4b (256 x 256): per-vocab trajectory
// ---------------------------------------------------------------------------
__global__ __launch_bounds__(256)
void s4b_kernel()
{
    __shared__ float red[256];
    __shared__ float sdist[256];
    __shared__ int   sidx[256];
    __shared__ int   memIdx[DEPTH_];
    __shared__ float wsh[DEPTH_];
    __shared__ float shconf;

    const int v = blockIdx.x, tid = threadIdx.x;

    float part = 0.f;
    for (int i = tid; i < TD_; i += 256) { float z = g_z0[(size_t)v*TD_ + i]; part += z*z; }
    red[tid] = part; __syncthreads();
    for (int st = 128; st > 0; st >>= 1) { if (tid < st) red[tid] += red[tid+st]; __syncthreads(); }
    float z2 = red[0];
    __syncthreads();

    float bd = 1e30f; int bi = 0;
    for (int kp = tid; kp < NSYM_; kp += 256) {
        float d = z2 + g_sym2[kp] - 2.f*g_Z0S[(size_t)v*NSYM_ + kp];
        if (d < bd) { bd = d; bi = kp; }
    }
    sdist[tid] = bd; sidx[tid] = bi; __syncthreads();
    for (int st = 128; st > 0; st >>= 1) {
        if (tid < st) {
            float d2 = sdist[tid+st]; int i2 = sidx[tid+st];
            if (d2 < sdist[tid] || (d2 == sdist[tid] && i2 < sidx[tid])) { sdist[tid] = d2; sidx[tid] = i2; }
        }
        __syncthreads();
    }
    int si = sidx[0]; float sd = sdist[0];
    if (tid == 0) { memIdx[0] = si; shconf = 1.f/(1.f + sd); }
    float symL = sd;
    float conL = g_conDist[si];
    __syncthreads();

    for (int d = 1; d < DEPTH_; d++) {
        int k = memIdx[d-1];
        if (tid == 0) {
            float sc[DEPTH_]; float mx = -1e30f;
            float cf = shconf;
            for (int j = 0; j < d; j++) {
                float s = g_QK[(size_t)k*NSYM_ + memIdx[j]] * SCALE_ * cf;
                sc[j] = s; if (s > mx) mx = s;
            }
            float se = 0.f;
            for (int j = 0; j < d; j++) { sc[j] = expf(sc[j]-mx); se += sc[j]; }
            for (int j = 0; j < d; j++) wsh[j] = sc[j]/se;
        }
        __syncthreads();

        part = 0.f;
        for (int i = tid; i < TD_; i += 256) {
            float z = g_cellTab[(size_t)k*TD_ + i];
            for (int j = 0; j < d; j++)
                z += 0.1f * wsh[j] * g_Vsym[(size_t)memIdx[j]*TD_ + i];
            part += z*z;
        }
        red[tid] = part; __syncthreads();
        for (int st = 128; st > 0; st >>= 1) { if (tid < st) red[tid] += red[tid+st]; __syncthreads(); }
        z2 = red[0];
        __syncthreads();

        bd = 1e30f; bi = 0;
        for (int kp = tid; kp < NSYM_; kp += 256) {
            float zdot = g_CS[(size_t)k*NSYM_ + kp];
            for (int j = 0; j < d; j++)
                zdot += 0.1f * wsh[j] * g_VS[(size_t)memIdx[j]*NSYM_ + kp];
            float dist = z2 + g_sym2[kp] - 2.f*zdot;
            if (dist < bd) { bd = dist; bi = kp; }
        }
        sdist[tid] = bd; sidx[tid] = bi; __syncthreads();
        for (int st = 128; st > 0; st >>= 1) {
            if (tid < st) {
                float d2 = sdist[tid+st]; int i2 = sidx[tid+st];
                if (d2 < sdist[tid] || (d2 == sdist[tid] && i2 < sidx[tid])) { sdist[tid] = d2; sidx[tid] = i2; }
            }
            __syncthreads();
        }
        si = sidx[0]; sd = sdist[0];
        if (tid == 0) { memIdx[d] = si; shconf = 1.f/(1.f + sd); }
        symL += sd;
        conL += g_conDist[si];
        __syncthreads();
    }

    if (tid == 0) {
        g_fin[v]   = memIdx[DEPTH_-1];
        g_symLv[v] = symL;
        g_conLv[v] = conL;
    }
}

// ---------------------------------------------------------------------------
// Stage 5 (4097 x 256): output scatter + scalar losses
// ---------------------------------------------------------------------------
__global__ __launch_bounds__(256)
void s5_kernel(const int* __restrict__ x, float* __restrict__ out, int writeLoss)
{
    const int b = blockIdx.x, tid = threadIdx.x;

    if (b < 4096) {
        int gid = b * 256 + tid;
        int p = gid >> 6;
        int c = gid & 63;
        int v = __ldg(&x[p]);
        int f = g_fin[v];
        ((float4*)out)[gid] = ((const float4*)(g_lookOut + (size_t)f*NV_))[c];
    } else {
        __shared__ float red[256];
        float h = (float)g_hist[tid];
        float s = h * g_symLv[tid];
        float c = h * g_conLv[tid];

        red[tid] = s; __syncthreads();
        for (int st = 128; st > 0; st >>= 1) { if (tid < st) red[tid] += red[tid+st]; __syncthreads(); }
        float st_tot = red[0]; __syncthreads();

        red[tid] = c; __syncthreads();
        for (int st = 128; st > 0; st >>= 1) { if (tid < st) red[tid] += red[tid+st]; __syncthreads(); }
        float ct_tot = red[0];

        if (tid == 0 && writeLoss) {
            float norm = (1.f + CC_) / (float)((size_t)NPOS_ * TD_);
            out[(size_t)NPOS_*NV_]     = st_tot * norm;
            out[(size_t)NPOS_*NV_ + 1] = ct_tot * norm;
        }
    }
}

// ---------------------------------------------------------------------------
// Host launcher
// ---------------------------------------------------------------------------
extern "C" void kernel_launch(void* const* d_in, const int* in_sizes, int n_in,
                              void* d_out, int out_size)
{
    const int*   x     = (const int*)d_in[0];
    const float* mag   = (const float*)d_in[1];
    const float* phase = (const float*)d_in[2];
    const float* Wr    = (const float*)d_in[3];
    const float* Wi    = (const float*)d_in[4];
    const float* qw    = (const float*)d_in[5];
    const float* qb    = (const float*)d_in[6];
    const float* kw    = (const float*)d_in[7];
    const float* kb    = (const float*)d_in[8];
    const float* vw    = (const float*)d_in[9];
    const float* vb    = (const float*)d_in[10];
    const float* dec_w = (const float*)d_in[11];
    const float* dec_b = (const float*)d_in[12];
    const float* sym   = (const float*)d_in[13];
    const float* con   = (const float*)d_in[14];
    float* out = (float*)d_out;

    int writeLoss = (out_size >= NPOS_*NV_ + 2) ? 1 : 0;

    s0_kernel<<<417, 256>>>(mag, phase, Wr, Wi, sym, con, x);
    s1_kernel<<<256, 128>>>(sym, kw, kb);
    s2_kernel<<<320, 128>>>(sym, vw, vb, qw, qb);
    s3_kernel<<<352, 128>>>(sym);
    s4a_kernel<<<32, 128>>>(dec_w, dec_b);
    s4b_kernel<<<256, 256>>>();
    s5_kernel<<<4097, 256>>>(x, out, writeLoss);
}

// round 7
// speedup vs baseline: 1.0593x; 1.0593x over previous
#include <cuda_runtime.h>
#include <math.h>

// Problem constants
#define D_     512
#define TD_    1024
#define NSYM_  512
#define NCON_  64
#define NV_    256
#define NPOS_  16384
#define DEPTH_ 6
#define EPS_   1e-8f
#define CC_    0.25f
#define SCALE_ 0.04419417382415922f   // 512^-0.5

typedef unsigned long long ull;

// ---------------------------------------------------------------------------
// Static device scratch
// ---------------------------------------------------------------------------
__device__ float g_W2[TD_*TD_];
__device__ float g_embed[NV_*TD_];
__device__ float g_z0[NV_*TD_];
__device__ float g_cellTab[NSYM_*TD_];
__device__ float g_C2[NSYM_*TD_];
__device__ float g_C3[NSYM_*TD_];
__device__ float g_lookOut[NSYM_*NV_];
__device__ float g_Ksym[NSYM_*D_];
__device__ float g_Vsym[NSYM_*TD_];
__device__ float g_Qtab[NSYM_*D_];
__device__ float g_QK[NSYM_*NSYM_];
__device__ float g_CS[NSYM_*NSYM_];
__device__ float g_VS[NSYM_*NSYM_];
__device__ float g_Z0S[NV_*NSYM_];
__device__ float g_sym2[NSYM_];
__device__ float g_conDist[NSYM_];
__device__ int   g_hist[NV_];
__device__ int   g_fin[NV_];
__device__ float g_symLv[NV_];
__device__ float g_conLv[NV_];

// ---------------------------------------------------------------------------
// f32x2 helpers
// ---------------------------------------------------------------------------
union UF2 { ull u; float2 f; };

__device__ __forceinline__ void ffma2(ull &acc, ull a, ull b)
{
    asm("fma.rn.f32x2 %0, %1, %2, %0;" : "+l"(acc) : "l"(a), "l"(b));
}
__device__ __forceinline__ ull dup2(float v)
{
    ull r; asm("mov.b64 %0, {%1, %1};" : "=l"(r) : "f"(v)); return r;
}

// ---------------------------------------------------------------------------
// GEMM tile 128x64 (M x N), 256 threads, f32x2 micro-kernel.
// C[M,N] = A[M,K] @ B[N,K]^T (+bias).  CELL=1: B=W2int, cell epilogue.
// Thread (tx 0..15, ty 0..15): rows m0+ty*8..+7 (4 pairs), cols n0+tx*4..+3.
// smem: As[16][128] (k-major, rows contiguous), Bs[16][64].
// Per k-step: 2x LDS.128 (A pairs) + 1x LDS.128 (B) + 4 dup + 16 FFMA2.
// ---------------------------------------------------------------------------
#define TGSM (16*128 + 16*64)   // 3072 floats = 12 KB

template<int CELL>
__device__ __forceinline__ void dev_gemm(
    const float* __restrict__ A, const float* __restrict__ B,
    const float* __restrict__ bias, float* __restrict__ C,
    int N, int K, int bx, int by, float* smem)
{
    float (*As)[128] = (float (*)[128])smem;
    float (*Bs)[64]  = (float (*)[64])(smem + 16*128);

    const int tid = threadIdx.x;
    const int tx = tid & 15, ty = tid >> 4;
    const int m0 = by * 128, n0 = bx * 64;

    const int arow = tid & 127, akh = tid >> 7;   // A loader: row, k-half
    const int bcol = tid & 63,  bkq = tid >> 6;   // B loader: col, k-quarter

    const float* gA = A + (size_t)(m0 + arow) * K + akh * 8;
    const float* gB = B + (size_t)(n0 + bcol) * K + bkq * 4;

    ull acc[4][4];
#pragma unroll
    for (int i = 0; i < 4; i++)
#pragma unroll
        for (int j = 0; j < 4; j++) acc[i][j] = 0ull;

    const int nk = K >> 4;

    float4 pa0 = *(const float4*)(gA);
    float4 pa1 = *(const float4*)(gA + 4);
    float4 pb  = *(const float4*)(gB);

    for (int t = 0; t < nk; t++) {
        // store prefetched tile
#pragma unroll
        for (int c = 0; c < 4; c++) {
            As[akh*8 + c][arow]     = ((float*)&pa0)[c];
            As[akh*8 + 4 + c][arow] = ((float*)&pa1)[c];
        }
#pragma unroll
        for (int c = 0; c < 4; c++)
            Bs[bkq*4 + c][bcol] = ((float*)&pb)[c];
        __syncthreads();

        if (t + 1 < nk) {
            pa0 = *(const float4*)(gA + (t+1)*16);
            pa1 = *(const float4*)(gA + (t+1)*16 + 4);
            pb  = *(const float4*)(gB + (t+1)*16);
        }

#pragma unroll
        for (int kk = 0; kk < 16; kk++) {
            longlong2 A01 = *(const longlong2*)(&As[kk][ty*8]);
            longlong2 A23 = *(const longlong2*)(&As[kk][ty*8 + 4]);
            float4 bv = *(const float4*)(&Bs[kk][tx*4]);
            ull b0 = dup2(bv.x), b1 = dup2(bv.y), b2 = dup2(bv.z), b3 = dup2(bv.w);
            ull a0 = (ull)A01.x, a1 = (ull)A01.y, a2 = (ull)A23.x, a3 = (ull)A23.y;
            ffma2(acc[0][0], a0, b0); ffma2(acc[0][1], a0, b1);
            ffma2(acc[0][2], a0, b2); ffma2(acc[0][3], a0, b3);
            ffma2(acc[1][0], a1, b0); ffma2(acc[1][1], a1, b1);
            ffma2(acc[1][2], a1, b2); ffma2(acc[1][3], a1, b3);
            ffma2(acc[2][0], a2, b0); ffma2(acc[2][1], a2, b1);
            ffma2(acc[2][2], a2, b2); ffma2(acc[2][3], a2, b3);
            ffma2(acc[3][0], a3, b0); ffma2(acc[3][1], a3, b1);
            ffma2(acc[3][2], a3, b2); ffma2(acc[3][3], a3, b3);
        }
        __syncthreads();
    }

    if (!CELL) {
        float4 bb = make_float4(0.f, 0.f, 0.f, 0.f);
        if (bias) bb = *(const float4*)(bias + n0 + tx*4);
#pragma unroll
        for (int i = 0; i < 4; i++) {
            int r0 = m0 + ty*8 + 2*i;
            UF2 u0, u1, u2, u3;
            u0.u = acc[i][0]; u1.u = acc[i][1]; u2.u = acc[i][2]; u3.u = acc[i][3];
            float4 lo = make_float4(u0.f.x + bb.x, u1.f.x + bb.y, u2.f.x + bb.z, u3.f.x + bb.w);
            float4 hi = make_float4(u0.f.y + bb.x, u1.f.y + bb.y, u2.f.y + bb.z, u3.f.y + bb.w);
            *(float4*)(C + (size_t)r0*N + n0 + tx*4)     = lo;
            *(float4*)(C + (size_t)(r0+1)*N + n0 + tx*4) = hi;
        }
    } else {
        const int p0 = (n0 + tx*4) >> 1;   // cols (2p0,2p0+1),(2p0+2,2p0+3)
#pragma unroll
        for (int i = 0; i < 4; i++) {
            int r0 = m0 + ty*8 + 2*i;
            UF2 u0, u1, u2, u3;
            u0.u = acc[i][0]; u1.u = acc[i][1]; u2.u = acc[i][2]; u3.u = acc[i][3];
            {   // row r0, pair p0
                float lr = u0.f.x, li = u1.f.x;
                float mm = sqrtf(lr*lr + li*li + EPS_);
                C[(size_t)r0*TD_ + p0]      = tanhf(lr / (1.f + mm));
                C[(size_t)r0*TD_ + p0 + D_] = tanhf(li / (1.f + mm));
            }
            {   // row r0, pair p0+1
                float lr = u2.f.x, li = u3.f.x;
                float mm = sqrtf(lr*lr + li*li + EPS_);
                C[(size_t)r0*TD_ + p0 + 1]      = tanhf(lr / (1.f + mm));
                C[(size_t)r0*TD_ + p0 + 1 + D_] = tanhf(li / (1.f + mm));
            }
            {   // row r0+1, pair p0
                float lr = u0.f.y, li = u1.f.y;
                float mm = sqrtf(lr*lr + li*li + EPS_);
                C[(size_t)(r0+1)*TD_ + p0]      = tanhf(lr / (1.f + mm));
                C[(size_t)(r0+1)*TD_ + p0 + D_] = tanhf(li / (1.f + mm));
            }
            {   // row r0+1, pair p0+1
                float lr = u2.f.y, li = u3.f.y;
                float mm = sqrtf(lr*lr + li*li + EPS_);
                C[(size_t)(r0+1)*TD_ + p0 + 1]      = tanhf(lr / (1.f + mm));
                C[(size_t)(r0+1)*TD_ + p0 + 1 + D_] = tanhf(li / (1.f + mm));
            }
        }
    }
}

// ---------------------------------------------------------------------------
// Stage 0 (417 x 256): embed | W2int | sym2 | conDist | hist
// ---------------------------------------------------------------------------
__global__ __launch_bounds__(256)
void s0_kernel(const float* __restrict__ mag, const float* __restrict__ phase,
               const float* __restrict__ Wr,  const float* __restrict__ Wi,
               const float* __restrict__ sym, const float* __restrict__ con,
               const int* __restrict__ x)
{
    const int b = blockIdx.x, tid = threadIdx.x;

    if (b < 32) {
        int base = b * 8;
#pragma unroll
        for (int vv = 0; vv < 8; vv++) {
            int v = base + vv;
            for (int i = tid; i < D_; i += 256) {
                float r = mag[v*D_ + i];
                float t = phase[v*D_ + i];
                g_embed[v*TD_ + i]      = r * cosf(t);
                g_embed[v*TD_ + D_ + i] = r * sinf(t);
            }
        }
    } else if (b < 288) {
        int idx = b - 32;
        int k = tid * 4;
#pragma unroll
        for (int rr = 0; rr < 4; rr++) {
            int r = idx*4 + rr;
            int n = r >> 1;
            int odd = r & 1;
            float4 v;
            if (k < D_) {
                v = *(const float4*)((odd ? Wi : Wr) + (size_t)n*D_ + k);
            } else {
                int k2 = k - D_;
                if (odd) v = *(const float4*)(Wr + (size_t)n*D_ + k2);
                else {
                    v = *(const float4*)(Wi + (size_t)n*D_ + k2);
                    v.x = -v.x; v.y = -v.y; v.z = -v.z; v.w = -v.w;
                }
            }
            *(float4*)(g_W2 + (size_t)r*TD_ + k) = v;
        }
    } else if (b < 352) {
        int local = b - 288;
        int w = tid >> 5, lane = tid & 31;
        int row = local*8 + w;
        float s = 0.f;
        const float* src = sym + (size_t)row*TD_;
        for (int i = lane; i < TD_; i += 32) { float v = src[i]; s += v*v; }
#pragma unroll
        for (int o = 16; o > 0; o >>= 1) s += __shfl_down_sync(0xffffffffu, s, o);
        if (lane == 0) g_sym2[row] = s;
    } else if (b < 416) {
        int local = b - 352;
        int w = tid >> 5, lane = tid & 31;
        int row = local*8 + w;
        float sv[32];
#pragma unroll
        for (int c = 0; c < 32; c++) sv[c] = sym[(size_t)row*TD_ + c*32 + lane];
        float best = 1e30f;
        for (int j = 0; j < NCON_; j++) {
            const float* cj = con + (size_t)j*TD_;
            float s = 0.f;
#pragma unroll
            for (int c = 0; c < 32; c++) { float d = sv[c] - cj[c*32 + lane]; s += d*d; }
#pragma unroll
            for (int o = 16; o > 0; o >>= 1) s += __shfl_xor_sync(0xffffffffu, s, o);
            best = fminf(best, s);
        }
        if (lane == 0) g_conDist[row] = best;
    } else {
        __shared__ int hist[NV_];
        hist[tid] = 0; __syncthreads();
        for (int i = tid; i < NPOS_; i += 256) atomicAdd(&hist[x[i]], 1);
        __syncthreads();
        g_hist[tid] = hist[tid];
    }
}

// ---------------------------------------------------------------------------
// Stage 1 (192 x 256): cellTab(64) | z0(32) | Ksym(32) | Vsym(64)
// ---------------------------------------------------------------------------
__global__ __launch_bounds__(256)
void s1_kernel(const float* __restrict__ sym,
               const float* __restrict__ kw, const float* __restrict__ kb,
               const float* __restrict__ vw, const float* __restrict__ vb)
{
    __shared__ float sm[TGSM];
    const int b = blockIdx.x;
    if (b < 64) {
        dev_gemm<1>(sym, g_W2, nullptr, g_cellTab, TD_, TD_, b & 15, b >> 4, sm);
    } else if (b < 96) {
        int t = b - 64;
        dev_gemm<1>(g_embed, g_W2, nullptr, g_z0, TD_, TD_, t & 15, t >> 4, sm);
    } else if (b < 128) {
        int t = b - 96;
        dev_gemm<0>(sym, kw, kb, g_Ksym, D_, TD_, t & 7, t >> 3, sm);
    } else {
        int t = b - 128;
        dev_gemm<0>(sym, vw, vb, g_Vsym, TD_, TD_, t & 15, t >> 4, sm);
    }
}

// ---------------------------------------------------------------------------
// Stage 2 (176 x 256): C2(64) | Qtab(32) | CS(32) | VS(32) | Z0S(16)
// ---------------------------------------------------------------------------
__global__ __launch_bounds__(256)
void s2_kernel(const float* __restrict__ sym,
               const float* __restrict__ qw, const float* __restrict__ qb)
{
    __shared__ float sm[TGSM];
    const int b = blockIdx.x;
    if (b < 64) {
        dev_gemm<1>(g_cellTab, g_W2, nullptr, g_C2, TD_, TD_, b & 15, b >> 4, sm);
    } else if (b < 96) {
        int t = b - 64;
        dev_gemm<0>(g_cellTab, qw, qb, g_Qtab, D_, TD_, t & 7, t >> 3, sm);
    } else if (b < 128) {
        int t = b - 96;
        dev_gemm<0>(g_cellTab, sym, nullptr, g_CS, NSYM_, TD_, t & 7, t >> 3, sm);
    } else if (b < 160) {
        int t = b - 128;
        dev_gemm<0>(g_Vsym, sym, nullptr, g_VS, NSYM_, TD_, t & 7, t >> 3, sm);
    } else {
        int t = b - 160;
        dev_gemm<0>(g_z0, sym, nullptr, g_Z0S, NSYM_, TD_, t & 7, t >> 3, sm);
    }
}

// ---------------------------------------------------------------------------
// Stage 3 (96 x 256): C3(64) | QK(32)
// ---------------------------------------------------------------------------
__global__ __launch_bounds__(256)
void s3_kernel()
{
    __shared__ float sm[TGSM];
    const int b = blockIdx.x;
    if (b < 64) {
        dev_gemm<1>(g_C2, g_W2, nullptr, g_C3, TD_, TD_, b & 15, b >> 4, sm);
    } else {
        int t = b - 64;
        dev_gemm<0>(g_Qtab, g_Ksym, nullptr, g_QK, NSYM_, D_, t & 7, t >> 3, sm);
    }
}

// ---------------------------------------------------------------------------
// Trajectory device function (one block, vocab v), uses caller smem
// ---------------------------------------------------------------------------
__device__ void dev_trajectory(int v, float* sm)
{
    float* red   = sm;
    float* sdist = sm + 256;
    int*   sidx  = (int*)(sm + 512);
    int*   memIdx= (int*)(sm + 768);
    float* wsh   = sm + 776;
    float* shconf= sm + 784;
    const int tid = threadIdx.x;

    float part = 0.f;
    for (int i = tid; i < TD_; i += 256) { float z = g_z0[(size_t)v*TD_ + i]; part += z*z; }
    red[tid] = part; __syncthreads();
    for (int st = 128; st > 0; st >>= 1) { if (tid < st) red[tid] += red[tid+st]; __syncthreads(); }
    float z2 = red[0];
    __syncthreads();

    float bd = 1e30f; int bi = 0;
    for (int kp = tid; kp < NSYM_; kp += 256) {
        float d = z2 + g_sym2[kp] - 2.f*g_Z0S[(size_t)v*NSYM_ + kp];
        if (d < bd) { bd = d; bi = kp; }
    }
    sdist[tid] = bd; sidx[tid] = bi; __syncthreads();
    for (int st = 128; st > 0; st >>= 1) {
        if (tid < st) {
            float d2 = sdist[tid+st]; int i2 = sidx[tid+st];
            if (d2 < sdist[tid] || (d2 == sdist[tid] && i2 < sidx[tid])) { sdist[tid] = d2; sidx[tid] = i2; }
        }
        __syncthreads();
    }
    int si = sidx[0]; float sd = sdist[0];
    if (tid == 0) { memIdx[0] = si; shconf[0] = 1.f/(1.f + sd); }
    float symL = sd;
    float conL = g_conDist[si];
    __syncthreads();

    for (int d = 1; d < DEPTH_; d++) {
        int k = memIdx[d-1];
        if (tid == 0) {
            float sc[DEPTH_]; float mx = -1e30f;
            float cf = shconf[0];
            for (int j = 0; j < d; j++) {
                float s = g_QK[(size_t)k*NSYM_ + memIdx[j]] * SCALE_ * cf;
                sc[j] = s; if (s > mx) mx = s;
            }
            float se = 0.f;
            for (int j = 0; j < d; j++) { sc[j] = expf(sc[j]-mx); se += sc[j]; }
            for (int j = 0; j < d; j++) wsh[j] = sc[j]/se;
        }
        __syncthreads();

        part = 0.f;
        for (int i = tid; i < TD_; i += 256) {
            float z = g_cellTab[(size_t)k*TD_ + i];
            for (int j = 0; j < d; j++)
                z += 0.1f * wsh[j] * g_Vsym[(size_t)memIdx[j]*TD_ + i];
            part += z*z;
        }
        red[tid] = part; __syncthreads();
        for (int st = 128; st > 0; st >>= 1) { if (tid < st) red[tid] += red[tid+st]; __syncthreads(); }
        z2 = red[0];
        __syncthreads();

        bd = 1e30f; bi = 0;
        for (int kp = tid; kp < NSYM_; kp += 256) {
            float zdot = g_CS[(size_t)k*NSYM_ + kp];
            for (int j = 0; j < d; j++)
                zdot += 0.1f * wsh[j] * g_VS[(size_t)memIdx[j]*NSYM_ + kp];
            float dist = z2 + g_sym2[kp] - 2.f*zdot;
            if (dist < bd) { bd = dist; bi = kp; }
        }
        sdist[tid] = bd; sidx[tid] = bi; __syncthreads();
        for (int st = 128; st > 0; st >>= 1) {
            if (tid < st) {
                float d2 = sdist[tid+st]; int i2 = sidx[tid+st];
                if (d2 < sdist[tid] || (d2 == sdist[tid] && i2 < sidx[tid])) { sdist[tid] = d2; sidx[tid] = i2; }
            }
            __syncthreads();
        }
        si = sidx[0]; sd = sdist[0];
        if (tid == 0) { memIdx[d] = si; shconf[0] = 1.f/(1.f + sd); }
        symL += sd;
        conL += g_conDist[si];
        __syncthreads();
    }

    if (tid == 0) {
        g_fin[v]   = memIdx[DEPTH_-1];
        g_symLv[v] = symL;
        g_conLv[v] = conL;
    }
}

// ---------------------------------------------------------------------------
// Stage 4 (272 x 256): lookOut(16) | trajectory(256)
// ---------------------------------------------------------------------------
__global__ __launch_bounds__(256)
void s4_kernel(const float* __restrict__ dec_w, const float* __restrict__ dec_b)
{
    __shared__ float sm[TGSM];
    const int b = blockIdx.x;
    if (b < 16) {
        dev_gemm<0>(g_C3, dec_w, dec_b, g_lookOut, NV_, TD_, b & 3, b >> 2, sm);
    } else {
        dev_trajectory(b - 16, sm);
    }
}

// ---------------------------------------------------------------------------
// Stage 5 (4097 x 256): scatter + losses
// ---------------------------------------------------------------------------
__global__ __launch_bounds__(256)
void s5_kernel(const int* __restrict__ x, float* __restrict__ out, int writeLoss)
{
    const int b = blockIdx.x, tid = threadIdx.x;

    if (b < 4096) {
        int gid = b * 256 + tid;
        int p = gid >> 6;
        int c = gid & 63;
        int v = __ldg(&x[p]);
        int f = g_fin[v];
        ((float4*)out)[gid] = ((const float4*)(g_lookOut + (size_t)f*NV_))[c];
    } else {
        __shared__ float red[256];
        float h = (float)g_hist[tid];
        float s = h * g_symLv[tid];
        float c = h * g_conLv[tid];

        red[tid] = s; __syncthreads();
        for (int st = 128; st > 0; st >>= 1) { if (tid < st) red[tid] += red[tid+st]; __syncthreads(); }
        float st_tot = red[0]; __syncthreads();

        red[tid] = c; __syncthreads();
        for (int st = 128; st > 0; st >>= 1) { if (tid < st) red[tid] += red[tid+st]; __syncthreads(); }
        float ct_tot = red[0];

        if (tid == 0 && writeLoss) {
            float norm = (1.f + CC_) / (float)((size_t)NPOS_ * TD_);
            out[(size_t)NPOS_*NV_]     = st_tot * norm;
            out[(size_t)NPOS_*NV_ + 1] = ct_tot * norm;
        }
    }
}

// ---------------------------------------------------------------------------
// Host launcher
// ---------------------------------------------------------------------------
extern "C" void kernel_launch(void* const* d_in, const int* in_sizes, int n_in,
                              void* d_out, int out_size)
{
    const int*   x     = (const int*)d_in[0];
    const float* mag   = (const float*)d_in[1];
    const float* phase = (const float*)d_in[2];
    const float* Wr    = (const float*)d_in[3];
    const float* Wi    = (const float*)d_in[4];
    const float* qw    = (const float*)d_in[5];
    const float* qb    = (const float*)d_in[6];
    const float* kw    = (const float*)d_in[7];
    const float* kb    = (const float*)d_in[8];
    const float* vw    = (const float*)d_in[9];
    const float* vb    = (const float*)d_in[10];
    const float* dec_w = (const float*)d_in[11];
    const float* dec_b = (const float*)d_in[12];
    const float* sym   = (const float*)d_in[13];
    const float* con   = (const float*)d_in[14];
    float* out = (float*)d_out;

    int writeLoss = (out_size >= NPOS_*NV_ + 2) ? 1 : 0;

    s0_kernel<<<417, 256>>>(mag, phase, Wr, Wi, sym, con, x);
    s1_kernel<<<192, 256>>>(sym, kw, kb, vw, vb);
    s2_kernel<<<176, 256>>>(sym, qw, qb);
    s3_kernel<<<96, 256>>>();
    s4_kernel<<<272, 256>>>(dec_w, dec_b);
    s5_kernel<<<4097, 256>>>(x, out, writeLoss);
}

// round 8
// speedup vs baseline: 1.2338x; 1.1647x over previous
#include <cuda_runtime.h>
#include <math.h>

// Problem constants
#define D_     512
#define TD_    1024
#define NSYM_  512
#define NCON_  64
#define NV_    256
#define NPOS_  16384
#define DEPTH_ 6
#define EPS_   1e-8f
#define CC_    0.25f
#define SCALE_ 0.04419417382415922f   // 512^-0.5

#define NBLOCKS 296   // 2 blocks/SM x 148 SMs, guaranteed resident

typedef unsigned long long ull;

// ---------------------------------------------------------------------------
// Static device scratch
// ---------------------------------------------------------------------------
__device__ float g_W2[TD_*TD_];
__device__ float g_embed[NV_*TD_];
__device__ float g_z0[NV_*TD_];
__device__ float g_cellTab[NSYM_*TD_];
__device__ float g_C2[NSYM_*TD_];
__device__ float g_C3[NSYM_*TD_];
__device__ float g_lookOut[NSYM_*NV_];
__device__ float g_Ksym[NSYM_*D_];
__device__ float g_Vsym[NSYM_*TD_];
__device__ float g_Qtab[NSYM_*D_];
__device__ float g_QK[NSYM_*NSYM_];
__device__ float g_CS[NSYM_*NSYM_];
__device__ float g_VS[NSYM_*NSYM_];
__device__ float g_Z0S[NV_*NSYM_];
__device__ float g_sym2[NSYM_];
__device__ float g_conDist[NSYM_];
__device__ int   g_hist[NV_];
__device__ int   g_fin[NV_];
__device__ float g_symLv[NV_];
__device__ float g_conLv[NV_];
__device__ ull   g_barCnt;          // monotone grid-barrier counter

// ---------------------------------------------------------------------------
// Grid-wide barrier (all NBLOCKS resident; monotone counter, replay-safe)
// ---------------------------------------------------------------------------
__device__ __forceinline__ void grid_barrier()
{
    __syncthreads();
    if (threadIdx.x == 0) {
        __threadfence();
        ull t = atomicAdd(&g_barCnt, 1ULL) + 1ULL;
        ull target = ((t - 1ULL) / NBLOCKS + 1ULL) * NBLOCKS;
        while (*(volatile ull*)&g_barCnt < target) { }
        __threadfence();
    }
    __syncthreads();
}

// ---------------------------------------------------------------------------
// f32x2 helpers
// ---------------------------------------------------------------------------
union UF2 { ull u; float2 f; };

__device__ __forceinline__ void ffma2(ull &acc, ull a, ull b)
{
    asm("fma.rn.f32x2 %0, %1, %2, %0;" : "+l"(acc) : "l"(a), "l"(b));
}
__device__ __forceinline__ ull dup2(float v)
{
    ull r; asm("mov.b64 %0, {%1, %1};" : "=l"(r) : "f"(v)); return r;
}

// ---------------------------------------------------------------------------
// GEMM tile 128x64 (M x N), 256 threads, f32x2 micro-kernel.
// C[M,N] = A[M,K] @ B[N,K]^T (+bias).  CELL=1: B=W2int, cell epilogue.
// ---------------------------------------------------------------------------
#define TGSM (16*128 + 16*64)   // 3072 floats = 12 KB

template<int CELL>
__device__ __forceinline__ void dev_gemm(
    const float* __restrict__ A, const float* __restrict__ B,
    const float* __restrict__ bias, float* __restrict__ C,
    int N, int K, int bx, int by, float* smem)
{
    float (*As)[128] = (float (*)[128])smem;
    float (*Bs)[64]  = (float (*)[64])(smem + 16*128);

    const int tid = threadIdx.x;
    const int tx = tid & 15, ty = tid >> 4;
    const int m0 = by * 128, n0 = bx * 64;

    const int arow = tid & 127, akh = tid >> 7;
    const int bcol = tid & 63,  bkq = tid >> 6;

    const float* gA = A + (size_t)(m0 + arow) * K + akh * 8;
    const float* gB = B + (size_t)(n0 + bcol) * K + bkq * 4;

    ull acc[4][4];
#pragma unroll
    for (int i = 0; i < 4; i++)
#pragma unroll
        for (int j = 0; j < 4; j++) acc[i][j] = 0ull;

    const int nk = K >> 4;

    float4 pa0 = *(const float4*)(gA);
    float4 pa1 = *(const float4*)(gA + 4);
    float4 pb  = *(const float4*)(gB);

    for (int t = 0; t < nk; t++) {
#pragma unroll
        for (int c = 0; c < 4; c++) {
            As[akh*8 + c][arow]     = ((float*)&pa0)[c];
            As[akh*8 + 4 + c][arow] = ((float*)&pa1)[c];
        }
#pragma unroll
        for (int c = 0; c < 4; c++)
            Bs[bkq*4 + c][bcol] = ((float*)&pb)[c];
        __syncthreads();

        if (t + 1 < nk) {
            pa0 = *(const float4*)(gA + (t+1)*16);
            pa1 = *(const float4*)(gA + (t+1)*16 + 4);
            pb  = *(const float4*)(gB + (t+1)*16);
        }

#pragma unroll
        for (int kk = 0; kk < 16; kk++) {
            longlong2 A01 = *(const longlong2*)(&As[kk][ty*8]);
            longlong2 A23 = *(const longlong2*)(&As[kk][ty*8 + 4]);
            float4 bv = *(const float4*)(&Bs[kk][tx*4]);
            ull b0 = dup2(bv.x), b1 = dup2(bv.y), b2 = dup2(bv.z), b3 = dup2(bv.w);
            ull a0 = (ull)A01.x, a1 = (ull)A01.y, a2 = (ull)A23.x, a3 = (ull)A23.y;
            ffma2(acc[0][0], a0, b0); ffma2(acc[0][1], a0, b1);
            ffma2(acc[0][2], a0, b2); ffma2(acc[0][3], a0, b3);
            ffma2(acc[1][0], a1, b0); ffma2(acc[1][1], a1, b1);
            ffma2(acc[1][2], a1, b2); ffma2(acc[1][3], a1, b3);
            ffma2(acc[2][0], a2, b0); ffma2(acc[2][1], a2, b1);
            ffma2(acc[2][2], a2, b2); ffma2(acc[2][3], a2, b3);
            ffma2(acc[3][0], a3, b0); ffma2(acc[3][1], a3, b1);
            ffma2(acc[3][2], a3, b2); ffma2(acc[3][3], a3, b3);
        }
        __syncthreads();
    }

    if (!CELL) {
        float4 bb = make_float4(0.f, 0.f, 0.f, 0.f);
        if (bias) bb = *(const float4*)(bias + n0 + tx*4);
#pragma unroll
        for (int i = 0; i < 4; i++) {
            int r0 = m0 + ty*8 + 2*i;
            UF2 u0, u1, u2, u3;
            u0.u = acc[i][0]; u1.u = acc[i][1]; u2.u = acc[i][2]; u3.u = acc[i][3];
            float4 lo = make_float4(u0.f.x + bb.x, u1.f.x + bb.y, u2.f.x + bb.z, u3.f.x + bb.w);
            float4 hi = make_float4(u0.f.y + bb.x, u1.f.y + bb.y, u2.f.y + bb.z, u3.f.y + bb.w);
            *(float4*)(C + (size_t)r0*N + n0 + tx*4)     = lo;
            *(float4*)(C + (size_t)(r0+1)*N + n0 + tx*4) = hi;
        }
    } else {
        const int p0 = (n0 + tx*4) >> 1;
#pragma unroll
        for (int i = 0; i < 4; i++) {
            int r0 = m0 + ty*8 + 2*i;
            UF2 u0, u1, u2, u3;
            u0.u = acc[i][0]; u1.u = acc[i][1]; u2.u = acc[i][2]; u3.u = acc[i][3];
            {
                float lr = u0.f.x, li = u1.f.x;
                float mm = sqrtf(lr*lr + li*li + EPS_);
                C[(size_t)r0*TD_ + p0]      = tanhf(lr / (1.f + mm));
                C[(size_t)r0*TD_ + p0 + D_] = tanhf(li / (1.f + mm));
            }
            {
                float lr = u2.f.x, li = u3.f.x;
                float mm = sqrtf(lr*lr + li*li + EPS_);
                C[(size_t)r0*TD_ + p0 + 1]      = tanhf(lr / (1.f + mm));
                C[(size_t)r0*TD_ + p0 + 1 + D_] = tanhf(li / (1.f + mm));
            }
            {
                float lr = u0.f.y, li = u1.f.y;
                float mm = sqrtf(lr*lr + li*li + EPS_);
                C[(size_t)(r0+1)*TD_ + p0]      = tanhf(lr / (1.f + mm));
                C[(size_t)(r0+1)*TD_ + p0 + D_] = tanhf(li / (1.f + mm));
            }
            {
                float lr = u2.f.y, li = u3.f.y;
                float mm = sqrtf(lr*lr + li*li + EPS_);
                C[(size_t)(r0+1)*TD_ + p0 + 1]      = tanhf(lr / (1.f + mm));
                C[(size_t)(r0+1)*TD_ + p0 + 1 + D_] = tanhf(li / (1.f + mm));
            }
        }
    }
}

// ---------------------------------------------------------------------------
// Prep unit (417 units)
// ---------------------------------------------------------------------------
__device__ void dev_prep(int b, const float* __restrict__ mag,
                         const float* __restrict__ phase,
                         const float* __restrict__ Wr, const float* __restrict__ Wi,
                         const float* __restrict__ sym, const float* __restrict__ con,
                         const int* __restrict__ x, float* sm)
{
    const int tid = threadIdx.x;

    if (b < 32) {
        int base = b * 8;
#pragma unroll
        for (int vv = 0; vv < 8; vv++) {
            int v = base + vv;
            for (int i = tid; i < D_; i += 256) {
                float r = mag[v*D_ + i];
                float t = phase[v*D_ + i];
                g_embed[v*TD_ + i]      = r * cosf(t);
                g_embed[v*TD_ + D_ + i] = r * sinf(t);
            }
        }
    } else if (b < 288) {
        int idx = b - 32;
        int k = tid * 4;
#pragma unroll
        for (int rr = 0; rr < 4; rr++) {
            int r = idx*4 + rr;
            int n = r >> 1;
            int odd = r & 1;
            float4 v;
            if (k < D_) {
                v = *(const float4*)((odd ? Wi : Wr) + (size_t)n*D_ + k);
            } else {
                int k2 = k - D_;
                if (odd) v = *(const float4*)(Wr + (size_t)n*D_ + k2);
                else {
                    v = *(const float4*)(Wi + (size_t)n*D_ + k2);
                    v.x = -v.x; v.y = -v.y; v.z = -v.z; v.w = -v.w;
                }
            }
            *(float4*)(g_W2 + (size_t)r*TD_ + k) = v;
        }
    } else if (b < 352) {
        int local = b - 288;
        int w = tid >> 5, lane = tid & 31;
        int row = local*8 + w;
        float s = 0.f;
        const float* src = sym + (size_t)row*TD_;
        for (int i = lane; i < TD_; i += 32) { float v = src[i]; s += v*v; }
#pragma unroll
        for (int o = 16; o > 0; o >>= 1) s += __shfl_down_sync(0xffffffffu, s, o);
        if (lane == 0) g_sym2[row] = s;
    } else if (b < 416) {
        int local = b - 352;
        int w = tid >> 5, lane = tid & 31;
        int row = local*8 + w;
        float sv[32];
#pragma unroll
        for (int c = 0; c < 32; c++) sv[c] = sym[(size_t)row*TD_ + c*32 + lane];
        float best = 1e30f;
        for (int j = 0; j < NCON_; j++) {
            const float* cj = con + (size_t)j*TD_;
            float s = 0.f;
#pragma unroll
            for (int c = 0; c < 32; c++) { float d = sv[c] - cj[c*32 + lane]; s += d*d; }
#pragma unroll
            for (int o = 16; o > 0; o >>= 1) s += __shfl_xor_sync(0xffffffffu, s, o);
            best = fminf(best, s);
        }
        if (lane == 0) g_conDist[row] = best;
    } else {
        int* hist = (int*)sm;
        hist[tid] = 0; __syncthreads();
        for (int i = tid; i < NPOS_; i += 256) atomicAdd(&hist[x[i]], 1);
        __syncthreads();
        g_hist[tid] = hist[tid];
        __syncthreads();
    }
}

// ---------------------------------------------------------------------------
// Trajectory (one unit = one vocab id, 256 threads)
// ---------------------------------------------------------------------------
__device__ void dev_trajectory(int v, float* sm)
{
    float* red   = sm;
    float* sdist = sm + 256;
    int*   sidx  = (int*)(sm + 512);
    int*   memIdx= (int*)(sm + 768);
    float* wsh   = sm + 776;
    float* shconf= sm + 784;
    const int tid = threadIdx.x;

    float part = 0.f;
    for (int i = tid; i < TD_; i += 256) { float z = g_z0[(size_t)v*TD_ + i]; part += z*z; }
    red[tid] = part; __syncthreads();
    for (int st = 128; st > 0; st >>= 1) { if (tid < st) red[tid] += red[tid+st]; __syncthreads(); }
    float z2 = red[0];
    __syncthreads();

    float bd = 1e30f; int bi = 0;
    for (int kp = tid; kp < NSYM_; kp += 256) {
        float d = z2 + g_sym2[kp] - 2.f*g_Z0S[(size_t)v*NSYM_ + kp];
        if (d < bd) { bd = d; bi = kp; }
    }
    sdist[tid] = bd; sidx[tid] = bi; __syncthreads();
    for (int st = 128; st > 0; st >>= 1) {
        if (tid < st) {
            float d2 = sdist[tid+st]; int i2 = sidx[tid+st];
            if (d2 < sdist[tid] || (d2 == sdist[tid] && i2 < sidx[tid])) { sdist[tid] = d2; sidx[tid] = i2; }
        }
        __syncthreads();
    }
    int si = sidx[0]; float sd = sdist[0];
    if (tid == 0) { memIdx[0] = si; shconf[0] = 1.f/(1.f + sd); }
    float symL = sd;
    float conL = g_conDist[si];
    __syncthreads();

    for (int d = 1; d < DEPTH_; d++) {
        int k = memIdx[d-1];
        if (tid == 0) {
            float sc[DEPTH_]; float mx = -1e30f;
            float cf = shconf[0];
            for (int j = 0; j < d; j++) {
                float s = g_QK[(size_t)k*NSYM_ + memIdx[j]] * SCALE_ * cf;
                sc[j] = s; if (s > mx) mx = s;
            }
            float se = 0.f;
            for (int j = 0; j < d; j++) { sc[j] = expf(sc[j]-mx); se += sc[j]; }
            for (int j = 0; j < d; j++) wsh[j] = sc[j]/se;
        }
        __syncthreads();

        part = 0.f;
        for (int i = tid; i < TD_; i += 256) {
            float z = g_cellTab[(size_t)k*TD_ + i];
            for (int j = 0; j < d; j++)
                z += 0.1f * wsh[j] * g_Vsym[(size_t)memIdx[j]*TD_ + i];
            part += z*z;
        }
        red[tid] = part; __syncthreads();
        for (int st = 128; st > 0; st >>= 1) { if (tid < st) red[tid] += red[tid+st]; __syncthreads(); }
        z2 = red[0];
        __syncthreads();

        bd = 1e30f; bi = 0;
        for (int kp = tid; kp < NSYM_; kp += 256) {
            float zdot = g_CS[(size_t)k*NSYM_ + kp];
            for (int j = 0; j < d; j++)
                zdot += 0.1f * wsh[j] * g_VS[(size_t)memIdx[j]*NSYM_ + kp];
            float dist = z2 + g_sym2[kp] - 2.f*zdot;
            if (dist < bd) { bd = dist; bi = kp; }
        }
        sdist[tid] = bd; sidx[tid] = bi; __syncthreads();
        for (int st = 128; st > 0; st >>= 1) {
            if (tid < st) {
                float d2 = sdist[tid+st]; int i2 = sidx[tid+st];
                if (d2 < sdist[tid] || (d2 == sdist[tid] && i2 < sidx[tid])) { sdist[tid] = d2; sidx[tid] = i2; }
            }
            __syncthreads();
        }
        si = sidx[0]; sd = sdist[0];
        if (tid == 0) { memIdx[d] = si; shconf[0] = 1.f/(1.f + sd); }
        symL += sd;
        conL += g_conDist[si];
        __syncthreads();
    }

    if (tid == 0) {
        g_fin[v]   = memIdx[DEPTH_-1];
        g_symLv[v] = symL;
        g_conLv[v] = conL;
    }
    __syncthreads();
}

// ---------------------------------------------------------------------------
// Persistent mega-kernel: all levels with grid barriers in between
// ---------------------------------------------------------------------------
__global__ __launch_bounds__(256, 2)
void mega_kernel(const int* __restrict__ x,
                 const float* __restrict__ mag, const float* __restrict__ phase,
                 const float* __restrict__ Wr,  const float* __restrict__ Wi,
                 const float* __restrict__ qw,  const float* __restrict__ qb,
                 const float* __restrict__ kw,  const float* __restrict__ kb,
                 const float* __restrict__ vw,  const float* __restrict__ vb,
                 const float* __restrict__ dec_w, const float* __restrict__ dec_b,
                 const float* __restrict__ sym, const float* __restrict__ con,
                 float* __restrict__ out, int writeLoss)
{
    __shared__ float sm[TGSM];
    const int b0 = blockIdx.x;

    // ---- L0: prep (417 units) ----
    for (int u = b0; u < 417; u += NBLOCKS)
        dev_prep(u, mag, phase, Wr, Wi, sym, con, x, sm);
    grid_barrier();

    // ---- L1 (192): cellTab(64) | z0(32) | Ksym(32) | Vsym(64) ----
    for (int u = b0; u < 192; u += NBLOCKS) {
        if (u < 64) {
            dev_gemm<1>(sym, g_W2, nullptr, g_cellTab, TD_, TD_, u & 15, u >> 4, sm);
        } else if (u < 96) {
            int t = u - 64;
            dev_gemm<1>(g_embed, g_W2, nullptr, g_z0, TD_, TD_, t & 15, t >> 4, sm);
        } else if (u < 128) {
            int t = u - 96;
            dev_gemm<0>(sym, kw, kb, g_Ksym, D_, TD_, t & 7, t >> 3, sm);
        } else {
            int t = u - 128;
            dev_gemm<0>(sym, vw, vb, g_Vsym, TD_, TD_, t & 15, t >> 4, sm);
        }
    }
    grid_barrier();

    // ---- L2 (176): C2(64) | Qtab(32) | CS(32) | VS(32) | Z0S(16) ----
    for (int u = b0; u < 176; u += NBLOCKS) {
        if (u < 64) {
            dev_gemm<1>(g_cellTab, g_W2, nullptr, g_C2, TD_, TD_, u & 15, u >> 4, sm);
        } else if (u < 96) {
            int t = u - 64;
            dev_gemm<0>(g_cellTab, qw, qb, g_Qtab, D_, TD_, t & 7, t >> 3, sm);
        } else if (u < 128) {
            int t = u - 96;
            dev_gemm<0>(g_cellTab, sym, nullptr, g_CS, NSYM_, TD_, t & 7, t >> 3, sm);
        } else if (u < 160) {
            int t = u - 128;
            dev_gemm<0>(g_Vsym, sym, nullptr, g_VS, NSYM_, TD_, t & 7, t >> 3, sm);
        } else {
            int t = u - 160;
            dev_gemm<0>(g_z0, sym, nullptr, g_Z0S, NSYM_, TD_, t & 7, t >> 3, sm);
        }
    }
    grid_barrier();

    // ---- L3 (96): C3(64) | QK(32) ----
    for (int u = b0; u < 96; u += NBLOCKS) {
        if (u < 64) {
            dev_gemm<1>(g_C2, g_W2, nullptr, g_C3, TD_, TD_, u & 15, u >> 4, sm);
        } else {
            int t = u - 64;
            dev_gemm<0>(g_Qtab, g_Ksym, nullptr, g_QK, NSYM_, D_, t & 7, t >> 3, sm);
        }
    }
    grid_barrier();

    // ---- L4 (272): lookOut(16) | trajectory(256) ----
    for (int u = b0; u < 272; u += NBLOCKS) {
        if (u < 16) {
            dev_gemm<0>(g_C3, dec_w, dec_b, g_lookOut, NV_, TD_, u & 3, u >> 2, sm);
        } else {
            dev_trajectory(u - 16, sm);
        }
    }
    grid_barrier();

    // ---- L5 (4097): scatter(4096) | losses(1) ----
    for (int u = b0; u < 4097; u += NBLOCKS) {
        const int tid = threadIdx.x;
        if (u < 4096) {
            int gid = u * 256 + tid;
            int p = gid >> 6;
            int c = gid & 63;
            int v = __ldg(&x[p]);
            int f = g_fin[v];
            ((float4*)out)[gid] = ((const float4*)(g_lookOut + (size_t)f*NV_))[c];
        } else {
            float* red = sm;
            float h = (float)g_hist[tid];
            float s = h * g_symLv[tid];
            float c = h * g_conLv[tid];

            red[tid] = s; __syncthreads();
            for (int st = 128; st > 0; st >>= 1) { if (tid < st) red[tid] += red[tid+st]; __syncthreads(); }
            float st_tot = red[0]; __syncthreads();

            red[tid] = c; __syncthreads();
            for (int st = 128; st > 0; st >>= 1) { if (tid < st) red[tid] += red[tid+st]; __syncthreads(); }
            float ct_tot = red[0];

            if (tid == 0 && writeLoss) {
                float norm = (1.f + CC_) / (float)((size_t)NPOS_ * TD_);
                out[(size_t)NPOS_*NV_]     = st_tot * norm;
                out[(size_t)NPOS_*NV_ + 1] = ct_tot * norm;
            }
            __syncthreads();
        }
    }
}

// ---------------------------------------------------------------------------
// Host launcher
// ---------------------------------------------------------------------------
extern "C" void kernel_launch(void* const* d_in, const int* in_sizes, int n_in,
                              void* d_out, int out_size)
{
    const int*   x     = (const int*)d_in[0];
    const float* mag   = (const float*)d_in[1];
    const float* phase = (const float*)d_in[2];
    const float* Wr    = (const float*)d_in[3];
    const float* Wi    = (const float*)d_in[4];
    const float* qw    = (const float*)d_in[5];
    const float* qb    = (const float*)d_in[6];
    const float* kw    = (const float*)d_in[7];
    const float* kb    = (const float*)d_in[8];
    const float* vw    = (const float*)d_in[9];
    const float* vb    = (const float*)d_in[10];
    const float* dec_w = (const float*)d_in[11];
    const float* dec_b = (const float*)d_in[12];
    const float* sym   = (const float*)d_in[13];
    const float* con   = (const float*)d_in[14];
    float* out = (float*)d_out;

    int writeLoss = (out_size >= NPOS_*NV_ + 2) ? 1 : 0;

    mega_kernel<<<NBLOCKS, 256>>>(x, mag, phase, Wr, Wi, qw, qb, kw, kb,
                                  vw, vb, dec_w, dec_b, sym, con, out, writeLoss);
}

// round 10
// speedup vs baseline: 1.2817x; 1.0388x over previous
#include <cuda_runtime.h>
#include <math.h>

// Problem constants
#define D_     512
#define TD_    1024
#define NSYM_  512
#define NCON_  64
#define NV_    256
#define NPOS_  16384
#define DEPTH_ 6
#define EPS_   1e-8f
#define CC_    0.25f
#define SCALE_ 0.04419417382415922f   // 512^-0.5

#define NBLOCKS 296   // 2 blocks/SM x 148 SMs, guaranteed resident

typedef unsigned long long ull;
typedef unsigned int uint32;

// ---------------------------------------------------------------------------
// Static device scratch
// ---------------------------------------------------------------------------
__device__ float g_W2[TD_*TD_];
__device__ float g_embed[NV_*TD_];
__device__ float g_z0[NV_*TD_];
__device__ float g_cellTab[NSYM_*TD_];
__device__ float g_C2[NSYM_*TD_];
__device__ float g_C3[NSYM_*TD_];
__device__ float g_lookOut[NSYM_*NV_];
__device__ float g_Ksym[NSYM_*D_];
__device__ float g_Vsym[NSYM_*TD_];
__device__ float g_Qtab[NSYM_*D_];
__device__ float g_QK[NSYM_*NSYM_];
__device__ float g_CS[NSYM_*NSYM_];
__device__ float g_VS[NSYM_*NSYM_];
__device__ float g_Z0S[NV_*NSYM_];
__device__ float g_sym2[NSYM_];
__device__ float g_conDist[NSYM_];
__device__ int   g_hist[NV_];
__device__ int   g_fin[NV_];
__device__ float g_symLv[NV_];
__device__ float g_conLv[NV_];
__device__ ull   g_barCnt;

// ---------------------------------------------------------------------------
// Grid-wide barrier (all NBLOCKS resident; monotone counter, replay-safe)
// ---------------------------------------------------------------------------
__device__ __forceinline__ void grid_barrier()
{
    __syncthreads();
    if (threadIdx.x == 0) {
        __threadfence();
        ull t = atomicAdd(&g_barCnt, 1ULL) + 1ULL;
        ull target = ((t - 1ULL) / NBLOCKS + 1ULL) * NBLOCKS;
        while (*(volatile ull*)&g_barCnt < target) { }
        __threadfence();
    }
    __syncthreads();
}

// ---------------------------------------------------------------------------
// tf32 helpers
// ---------------------------------------------------------------------------
__device__ __forceinline__ void mma_tf32(float* d, const uint32* a, const uint32* b)
{
    asm volatile("mma.sync.aligned.m16n8k8.row.col.f32.tf32.tf32.f32 "
        "{%0,%1,%2,%3}, {%4,%5,%6,%7}, {%8,%9}, {%0,%1,%2,%3};"
        : "+f"(d[0]), "+f"(d[1]), "+f"(d[2]), "+f"(d[3])
        : "r"(a[0]), "r"(a[1]), "r"(a[2]), "r"(a[3]), "r"(b[0]), "r"(b[1]));
}

__device__ __forceinline__ void split_store(uint32* H, uint32* L, int idx, float4 v)
{
#pragma unroll
    for (int c = 0; c < 4; c++) {
        float f = ((float*)&v)[c];
        uint32 h; asm("cvt.rna.tf32.f32 %0, %1;" : "=r"(h) : "f"(f));
        float r = f - __uint_as_float(h);
        uint32 l; asm("cvt.rna.tf32.f32 %0, %1;" : "=r"(l) : "f"(r));
        H[idx + c] = h; L[idx + c] = l;
    }
}

// ---------------------------------------------------------------------------
// Tensor-core GEMM tile 128x64 (M x N), 256 threads (8 warps of 32x32).
// C[M,N] = A[M,K] @ B[N,K]^T (+bias), 3xTF32 for fp32-level accuracy.
// CELL=1: B = W2int, complex-cell epilogue writes to Zout[M, 1024].
// smem: Ah/Al [128][20], Bh/Bl [64][20] (stride 20 = conflict-free)
// ---------------------------------------------------------------------------
#define TGSM (2*128*20 + 2*64*20)   // 7680 words = 30 KB

template<int CELL>
__device__ void dev_gemm_tc(const float* __restrict__ A, const float* __restrict__ B,
                            const float* __restrict__ bias, float* __restrict__ C,
                            int N, int K, int bx, int by, float* sm)
{
    uint32* Ah = (uint32*)sm;
    uint32* Al = Ah + 128*20;
    uint32* Bh = Al + 128*20;
    uint32* Bl = Bh + 64*20;

    const int tid  = threadIdx.x;
    const int warp = tid >> 5, lane = tid & 31;
    const int g = lane >> 2, tg = lane & 3;
    const int wm = (warp & 3) * 32, wn = (warp >> 2) * 32;
    const int m0 = by * 128, n0 = bx * 64;

    // loaders: A has 512 float4 slots (2/thread), B has 256 (1/thread)
    const int ar0 = tid >> 2, aq = tid & 3;   // slot tid
    const int ar1 = ar0 + 64;                 // slot tid+256
    const int br  = tid >> 2;

    const float* gA0 = A + (size_t)(m0 + ar0) * K + aq * 4;
    const float* gA1 = A + (size_t)(m0 + ar1) * K + aq * 4;
    const float* gB  = B + (size_t)(n0 + br)  * K + aq * 4;

    float d[2][4][4];
#pragma unroll
    for (int i = 0; i < 2; i++)
#pragma unroll
        for (int j = 0; j < 4; j++)
#pragma unroll
            for (int c = 0; c < 4; c++) d[i][j][c] = 0.f;

    const int nk = K >> 4;
    float4 pa0 = *(const float4*)(gA0);
    float4 pa1 = *(const float4*)(gA1);
    float4 pb  = *(const float4*)(gB);

    for (int t = 0; t < nk; t++) {
        split_store(Ah, Al, ar0*20 + aq*4, pa0);
        split_store(Ah, Al, ar1*20 + aq*4, pa1);
        split_store(Bh, Bl, br*20 + aq*4, pb);
        __syncthreads();

        if (t + 1 < nk) {
            pa0 = *(const float4*)(gA0 + (t+1)*16);
            pa1 = *(const float4*)(gA1 + (t+1)*16);
            pb  = *(const float4*)(gB  + (t+1)*16);
        }

#pragma unroll
        for (int kf = 0; kf < 2; kf++) {
            const int kk = kf * 8;
            uint32 ah[2][4], al[2][4];
#pragma unroll
            for (int mf = 0; mf < 2; mf++) {
                int base = (wm + mf*16 + g)*20 + kk + tg;
                ah[mf][0] = Ah[base];         ah[mf][1] = Ah[base + 160];
                ah[mf][2] = Ah[base + 4];     ah[mf][3] = Ah[base + 164];
                al[mf][0] = Al[base];         al[mf][1] = Al[base + 160];
                al[mf][2] = Al[base + 4];     al[mf][3] = Al[base + 164];
            }
            uint32 bh[4][2], bl[4][2];
#pragma unroll
            for (int nf = 0; nf < 4; nf++) {
                int base = (wn + nf*8 + g)*20 + kk + tg;
                bh[nf][0] = Bh[base]; bh[nf][1] = Bh[base + 4];
                bl[nf][0] = Bl[base]; bl[nf][1] = Bl[base + 4];
            }
#pragma unroll
            for (int mf = 0; mf < 2; mf++)
#pragma unroll
                for (int nf = 0; nf < 4; nf++) {
                    mma_tf32(d[mf][nf], ah[mf], bh[nf]);
                    mma_tf32(d[mf][nf], al[mf], bh[nf]);
                    mma_tf32(d[mf][nf], ah[mf], bl[nf]);
                }
        }
        __syncthreads();
    }

    if (!CELL) {
#pragma unroll
        for (int mf = 0; mf < 2; mf++)
#pragma unroll
            for (int nf = 0; nf < 4; nf++) {
                int r = m0 + wm + mf*16 + g;
                int c = n0 + wn + nf*8 + 2*tg;
                float b0v = bias ? bias[c]   : 0.f;
                float b1v = bias ? bias[c+1] : 0.f;
                C[(size_t)r*N + c]       = d[mf][nf][0] + b0v;
                C[(size_t)r*N + c + 1]   = d[mf][nf][1] + b1v;
                C[(size_t)(r+8)*N + c]     = d[mf][nf][2] + b0v;
                C[(size_t)(r+8)*N + c + 1] = d[mf][nf][3] + b1v;
            }
    } else {
#pragma unroll
        for (int mf = 0; mf < 2; mf++)
#pragma unroll
            for (int nf = 0; nf < 4; nf++) {
                int r = m0 + wm + mf*16 + g;
                int p = ((n0 + wn + nf*8) >> 1) + tg;
                {
                    float lr = d[mf][nf][0], li = d[mf][nf][1];
                    float mm = sqrtf(lr*lr + li*li + EPS_);
                    C[(size_t)r*TD_ + p]      = tanhf(lr / (1.f + mm));
                    C[(size_t)r*TD_ + p + D_] = tanhf(li / (1.f + mm));
                }
                {
                    float lr = d[mf][nf][2], li = d[mf][nf][3];
                    float mm = sqrtf(lr*lr + li*li + EPS_);
                    C[(size_t)(r+8)*TD_ + p]      = tanhf(lr / (1.f + mm));
                    C[(size_t)(r+8)*TD_ + p + D_] = tanhf(li / (1.f + mm));
                }
            }
    }
}

// ---------------------------------------------------------------------------
// Prep unit (417 units)
// ---------------------------------------------------------------------------
__device__ void dev_prep(int b, const float* __restrict__ mag,
                         const float* __restrict__ phase,
                         const float* __restrict__ Wr, const float* __restrict__ Wi,
                         const float* __restrict__ sym, const float* __restrict__ con,
                         const int* __restrict__ x, float* sm)
{
    const int tid = threadIdx.x;

    if (b < 32) {
        int base = b * 8;
#pragma unroll
        for (int vv = 0; vv < 8; vv++) {
            int v = base + vv;
            for (int i = tid; i < D_; i += 256) {
                float r = mag[v*D_ + i];
                float t = phase[v*D_ + i];
                g_embed[v*TD_ + i]      = r * cosf(t);
                g_embed[v*TD_ + D_ + i] = r * sinf(t);
            }
        }
    } else if (b < 288) {
        int idx = b - 32;
        int k = tid * 4;
#pragma unroll
        for (int rr = 0; rr < 4; rr++) {
            int r = idx*4 + rr;
            int n = r >> 1;
            int odd = r & 1;
            float4 v;
            if (k < D_) {
                v = *(const float4*)((odd ? Wi : Wr) + (size_t)n*D_ + k);
            } else {
                int k2 = k - D_;
                if (odd) v = *(const float4*)(Wr + (size_t)n*D_ + k2);
                else {
                    v = *(const float4*)(Wi + (size_t)n*D_ + k2);
                    v.x = -v.x; v.y = -v.y; v.z = -v.z; v.w = -v.w;
                }
            }
            *(float4*)(g_W2 + (size_t)r*TD_ + k) = v;
        }
    } else if (b < 352) {
        int local = b - 288;
        int w = tid >> 5, lane = tid & 31;
        int row = local*8 + w;
        float s = 0.f;
        const float* src = sym + (size_t)row*TD_;
        for (int i = lane; i < TD_; i += 32) { float v = src[i]; s += v*v; }
#pragma unroll
        for (int o = 16; o > 0; o >>= 1) s += __shfl_down_sync(0xffffffffu, s, o);
        if (lane == 0) g_sym2[row] = s;
    } else if (b < 416) {
        int local = b - 352;
        int w = tid >> 5, lane = tid & 31;
        int row = local*8 + w;
        float sv[32];
#pragma unroll
        for (int c = 0; c < 32; c++) sv[c] = sym[(size_t)row*TD_ + c*32 + lane];
        float best = 1e30f;
        for (int j = 0; j < NCON_; j++) {
            const float* cj = con + (size_t)j*TD_;
            float s = 0.f;
#pragma unroll
            for (int c = 0; c < 32; c++) { float d = sv[c] - cj[c*32 + lane]; s += d*d; }
#pragma unroll
            for (int o = 16; o > 0; o >>= 1) s += __shfl_xor_sync(0xffffffffu, s, o);
            best = fminf(best, s);
        }
        if (lane == 0) g_conDist[row] = best;
    } else {
        int* hist = (int*)sm;
        hist[tid] = 0; __syncthreads();
        for (int i = tid; i < NPOS_; i += 256) atomicAdd(&hist[x[i]], 1);
        __syncthreads();
        g_hist[tid] = hist[tid];
        __syncthreads();
    }
}

// ---------------------------------------------------------------------------
// Trajectory (one unit = one vocab id, 256 threads)
// ---------------------------------------------------------------------------
__device__ void dev_trajectory(int v, float* sm)
{
    float* red   = sm;
    float* sdist = sm + 256;
    int*   sidx  = (int*)(sm + 512);
    int*   memIdx= (int*)(sm + 768);
    float* wsh   = sm + 776;
    float* shconf= sm + 784;
    const int tid = threadIdx.x;

    float part = 0.f;
    for (int i = tid; i < TD_; i += 256) { float z = g_z0[(size_t)v*TD_ + i]; part += z*z; }
    red[tid] = part; __syncthreads();
    for (int st = 128; st > 0; st >>= 1) { if (tid < st) red[tid] += red[tid+st]; __syncthreads(); }
    float z2 = red[0];
    __syncthreads();

    float bd = 1e30f; int bi = 0;
    for (int kp = tid; kp < NSYM_; kp += 256) {
        float d = z2 + g_sym2[kp] - 2.f*g_Z0S[(size_t)v*NSYM_ + kp];
        if (d < bd) { bd = d; bi = kp; }
    }
    sdist[tid] = bd; sidx[tid] = bi; __syncthreads();
    for (int st = 128; st > 0; st >>= 1) {
        if (tid < st) {
            float d2 = sdist[tid+st]; int i2 = sidx[tid+st];
            if (d2 < sdist[tid] || (d2 == sdist[tid] && i2 < sidx[tid])) { sdist[tid] = d2; sidx[tid] = i2; }
        }
        __syncthreads();
    }
    int si = sidx[0]; float sd = sdist[0];
    if (tid == 0) { memIdx[0] = si; shconf[0] = 1.f/(1.f + sd); }
    float symL = sd;
    float conL = g_conDist[si];
    __syncthreads();

    for (int d = 1; d < DEPTH_; d++) {
        int k = memIdx[d-1];
        if (tid == 0) {
            float sc[DEPTH_]; float mx = -1e30f;
            float cf = shconf[0];
            for (int j = 0; j < d; j++) {
                float s = g_QK[(size_t)k*NSYM_ + memIdx[j]] * SCALE_ * cf;
                sc[j] = s; if (s > mx) mx = s;
            }
            float se = 0.f;
            for (int j = 0; j < d; j++) { sc[j] = expf(sc[j]-mx); se += sc[j]; }
            for (int j = 0; j < d; j++) wsh[j] = sc[j]/se;
        }
        __syncthreads();

        part = 0.f;
        for (int i = tid; i < TD_; i += 256) {
            float z = g_cellTab[(size_t)k*TD_ + i];
            for (int j = 0; j < d; j++)
                z += 0.1f * wsh[j] * g_Vsym[(size_t)memIdx[j]*TD_ + i];
            part += z*z;
        }
        red[tid] = part; __syncthreads();
        for (int st = 128; st > 0; st >>= 1) { if (tid < st) red[tid] += red[tid+st]; __syncthreads(); }
        z2 = red[0];
        __syncthreads();

        bd = 1e30f; bi = 0;
        for (int kp = tid; kp < NSYM_; kp += 256) {
            float zdot = g_CS[(size_t)k*NSYM_ + kp];
            for (int j = 0; j < d; j++)
                zdot += 0.1f * wsh[j] * g_VS[(size_t)memIdx[j]*NSYM_ + kp];
            float dist = z2 + g_sym2[kp] - 2.f*zdot;
            if (dist < bd) { bd = dist; bi = kp; }
        }
        sdist[tid] = bd; sidx[tid] = bi; __syncthreads();
        for (int st = 128; st > 0; st >>= 1) {
            if (tid < st) {
                float d2 = sdist[tid+st]; int i2 = sidx[tid+st];
                if (d2 < sdist[tid] || (d2 == sdist[tid] && i2 < sidx[tid])) { sdist[tid] = d2; sidx[tid] = i2; }
            }
            __syncthreads();
        }
        si = sidx[0]; sd = sdist[0];
        if (tid == 0) { memIdx[d] = si; shconf[0] = 1.f/(1.f + sd); }
        symL += sd;
        conL += g_conDist[si];
        __syncthreads();
    }

    if (tid == 0) {
        g_fin[v]   = memIdx[DEPTH_-1];
        g_symLv[v] = symL;
        g_conLv[v] = conL;
    }
    __syncthreads();
}

// ---------------------------------------------------------------------------
// Persistent mega-kernel
// ---------------------------------------------------------------------------
__global__ __launch_bounds__(256, 2)
void mega_kernel(const int* __restrict__ x,
                 const float* __restrict__ mag, const float* __restrict__ phase,
                 const float* __restrict__ Wr,  const float* __restrict__ Wi,
                 const float* __restrict__ qw,  const float* __restrict__ qb,
                 const float* __restrict__ kw,  const float* __restrict__ kb,
                 const float* __restrict__ vw,  const float* __restrict__ vb,
                 const float* __restrict__ dec_w, const float* __restrict__ dec_b,
                 const float* __restrict__ sym, const float* __restrict__ con,
                 float* __restrict__ out, int writeLoss)
{
    __shared__ float sm[TGSM];
    const int b0 = blockIdx.x;

    // ---- L0: prep (417 units) ----
    for (int u = b0; u < 417; u += NBLOCKS)
        dev_prep(u, mag, phase, Wr, Wi, sym, con, x, sm);
    grid_barrier();

    // ---- L1 (192): cellTab(64) | z0(32) | Ksym(32) | Vsym(64) ----
    for (int u = b0; u < 192; u += NBLOCKS) {
        if (u < 64) {
            dev_gemm_tc<1>(sym, g_W2, nullptr, g_cellTab, TD_, TD_, u & 15, u >> 4, sm);
        } else if (u < 96) {
            int t = u - 64;
            dev_gemm_tc<1>(g_embed, g_W2, nullptr, g_z0, TD_, TD_, t & 15, t >> 4, sm);
        } else if (u < 128) {
            int t = u - 96;
            dev_gemm_tc<0>(sym, kw, kb, g_Ksym, D_, TD_, t & 7, t >> 3, sm);
        } else {
            int t = u - 128;
            dev_gemm_tc<0>(sym, vw, vb, g_Vsym, TD_, TD_, t & 15, t >> 4, sm);
        }
    }
    grid_barrier();

    // ---- L2 (176): C2(64) | Qtab(32) | CS(32) | VS(32) | Z0S(16) ----
    for (int u = b0; u < 176; u += NBLOCKS) {
        if (u < 64) {
            dev_gemm_tc<1>(g_cellTab, g_W2, nullptr, g_C2, TD_, TD_, u & 15, u >> 4, sm);
        } else if (u < 96) {
            int t = u - 64;
            dev_gemm_tc<0>(g_cellTab, qw, qb, g_Qtab, D_, TD_, t & 7, t >> 3, sm);
        } else if (u < 128) {
            int t = u - 96;
            dev_gemm_tc<0>(g_cellTab, sym, nullptr, g_CS, NSYM_, TD_, t & 7, t >> 3, sm);
        } else if (u < 160) {
            int t = u - 128;
            dev_gemm_tc<0>(g_Vsym, sym, nullptr, g_VS, NSYM_, TD_, t & 7, t >> 3, sm);
        } else {
            int t = u - 160;
            dev_gemm_tc<0>(g_z0, sym, nullptr, g_Z0S, NSYM_, TD_, t & 7, t >> 3, sm);
        }
    }
    grid_barrier();

    // ---- L3 (96): C3(64) | QK(32) ----
    for (int u = b0; u < 96; u += NBLOCKS) {
        if (u < 64) {
            dev_gemm_tc<1>(g_C2, g_W2, nullptr, g_C3, TD_, TD_, u & 15, u >> 4, sm);
        } else {
            int t = u - 64;
            dev_gemm_tc<0>(g_Qtab, g_Ksym, nullptr, g_QK, NSYM_, D_, t & 7, t >> 3, sm);
        }
    }
    grid_barrier();

    // ---- L4 (272): lookOut(16) | trajectory(256) ----
    for (int u = b0; u < 272; u += NBLOCKS) {
        if (u < 16) {
            dev_gemm_tc<0>(g_C3, dec_w, dec_b, g_lookOut, NV_, TD_, u & 3, u >> 2, sm);
        } else {
            dev_trajectory(u - 16, sm);
        }
    }
    grid_barrier();

    // ---- L5 (4097): scatter(4096) | losses(1) ----
    for (int u = b0; u < 4097; u += NBLOCKS) {
        const int tid = threadIdx.x;
        if (u < 4096) {
            int gid = u * 256 + tid;
            int p = gid >> 6;
            int c = gid & 63;
            int v = __ldg(&x[p]);
            int f = g_fin[v];
            ((float4*)out)[gid] = ((const float4*)(g_lookOut + (size_t)f*NV_))[c];
        } else {
            float* red = sm;
            float h = (float)g_hist[tid];
            float s = h * g_symLv[tid];
            float c = h * g_conLv[tid];

            red[tid] = s; __syncthreads();
            for (int st = 128; st > 0; st >>= 1) { if (tid < st) red[tid] += red[tid+st]; __syncthreads(); }
            float st_tot = red[0]; __syncthreads();

            red[tid] = c; __syncthreads();
            for (int st = 128; st > 0; st >>= 1) { if (tid < st) red[tid] += red[tid+st]; __syncthreads(); }
            float ct_tot = red[0];

            if (tid == 0 && writeLoss) {
                float norm = (1.f + CC_) / (float)((size_t)NPOS_ * TD_);
                out[(size_t)NPOS_*NV_]     = st_tot * norm;
                out[(size_t)NPOS_*NV_ + 1] = ct_tot * norm;
            }
            __syncthreads();
        }
    }
}

// ---------------------------------------------------------------------------
// Host launcher
// ---------------------------------------------------------------------------
extern "C" void kernel_launch(void* const* d_in, const int* in_sizes, int n_in,
                              void* d_out, int out_size)
{
    const int*   x     = (const int*)d_in[0];
    const float* mag   = (const float*)d_in[1];
    const float* phase = (const float*)d_in[2];
    const float* Wr    = (const float*)d_in[3];
    const float* Wi    = (const float*)d_in[4];
    const float* qw    = (const float*)d_in[5];
    const float* qb    = (const float*)d_in[6];
    const float* kw    = (const float*)d_in[7];
    const float* kb    = (const float*)d_in[8];
    const float* vw    = (const float*)d_in[9];
    const float* vb    = (const float*)d_in[10];
    const float* dec_w = (const float*)d_in[11];
    const float* dec_b = (const float*)d_in[12];
    const float* sym   = (const float*)d_in[13];
    const float* con   = (const float*)d_in[14];
    float* out = (float*)d_out;

    int writeLoss = (out_size >= NPOS_*NV_ + 2) ? 1 : 0;

    mega_kernel<<<NBLOCKS, 256>>>(x, mag, phase, Wr, Wi, qw, qb, kw, kb,
                                  vw, vb, dec_w, dec_b, sym, con, out, writeLoss);
}

// round 11
// speedup vs baseline: 1.5539x; 1.2124x over previous
#include <cuda_runtime.h>
#include <math.h>

// Problem constants
#define D_     512
#define TD_    1024
#define NSYM_  512
#define NCON_  64
#define NV_    256
#define NPOS_  16384
#define DEPTH_ 6
#define EPS_   1e-8f
#define CC_    0.25f
#define SCALE_ 0.04419417382415922f   // 512^-0.5

#define NBLOCKS 592    // 4 blocks/SM x 148 SMs, guaranteed resident
#define NTHR    128

typedef unsigned long long ull;
typedef unsigned int uint32;

// ---------------------------------------------------------------------------
// Static device scratch
// ---------------------------------------------------------------------------
__device__ float g_W2[TD_*TD_];
__device__ float g_embed[NV_*TD_];
__device__ float g_z0[NV_*TD_];
__device__ float g_cellTab[NSYM_*TD_];
__device__ float g_C2[NSYM_*TD_];
__device__ float g_C3[NSYM_*TD_];
__device__ float g_lookOut[NSYM_*NV_];
__device__ float g_Ksym[NSYM_*D_];
__device__ float g_Vsym[NSYM_*TD_];
__device__ float g_Qtab[NSYM_*D_];
__device__ float g_QK[NSYM_*NSYM_];
__device__ float g_CS[NSYM_*NSYM_];
__device__ float g_VS[NSYM_*NSYM_];
__device__ float g_Z0S[NV_*NSYM_];
__device__ float g_sym2[NSYM_];
__device__ float g_conDist[NSYM_];
__device__ int   g_hist[NV_];
__device__ int   g_fin[NV_];
__device__ float g_symLv[NV_];
__device__ float g_conLv[NV_];
__device__ ull   g_barCnt;

// ---------------------------------------------------------------------------
// Grid-wide barrier (all NBLOCKS resident; monotone counter, replay-safe)
// ---------------------------------------------------------------------------
__device__ __forceinline__ void grid_barrier()
{
    __syncthreads();
    if (threadIdx.x == 0) {
        __threadfence();
        ull t = atomicAdd(&g_barCnt, 1ULL) + 1ULL;
        ull target = ((t - 1ULL) / NBLOCKS + 1ULL) * NBLOCKS;
        while (*(volatile ull*)&g_barCnt < target) { }
        __threadfence();
    }
    __syncthreads();
}

// ---------------------------------------------------------------------------
// tf32 helpers
// ---------------------------------------------------------------------------
__device__ __forceinline__ void mma_tf32(float* d, const uint32* a, const uint32* b)
{
    asm volatile("mma.sync.aligned.m16n8k8.row.col.f32.tf32.tf32.f32 "
        "{%0,%1,%2,%3}, {%4,%5,%6,%7}, {%8,%9}, {%0,%1,%2,%3};"
        : "+f"(d[0]), "+f"(d[1]), "+f"(d[2]), "+f"(d[3])
        : "r"(a[0]), "r"(a[1]), "r"(a[2]), "r"(a[3]), "r"(b[0]), "r"(b[1]));
}

// Split one float4 (k = q*4 .. q*4+3 of a row) into hi/lo tf32 and store into
// the k-pair-reordered layout: pos(k) = (k>>3)*8 + (k&3)*2 + ((k>>2)&1)
// With k = q*4 + c: kgroup = q>>1, hi = q&1, tg = c.
__device__ __forceinline__ void split_store22(uint32* H, uint32* L, int rowBase,
                                              int q, float4 v)
{
    int base = rowBase + (q >> 1) * 8 + (q & 1);
#pragma unroll
    for (int c = 0; c < 4; c++) {
        float f = ((float*)&v)[c];
        uint32 h; asm("cvt.rna.tf32.f32 %0, %1;" : "=r"(h) : "f"(f));
        float r = f - __uint_as_float(h);
        uint32 l; asm("cvt.rna.tf32.f32 %0, %1;" : "=r"(l) : "f"(r));
        H[base + c*2] = h; L[base + c*2] = l;
    }
}

// ---------------------------------------------------------------------------
// Tensor-core GEMM tile 64x64, 128 threads (4 warps of 32x32), 3xTF32.
// C[M,N] = A[M,K] @ B[N,K]^T (+bias). CELL=1: B=W2int, cell epilogue.
// smem: Ah/Al/Bh/Bl [64][22] with k-pair reorder -> fragment pairs via LDS.64
// ---------------------------------------------------------------------------
#define RS 22                      // row stride (words)
#define TGSM (4*64*RS)             // 5632 words = 22528 B

template<int CELL>
__device__ void dev_gemm_tc(const float* __restrict__ A, const float* __restrict__ B,
                            const float* __restrict__ bias, float* __restrict__ C,
                            int N, int K, int bx, int by, float* sm)
{
    uint32* Ah = (uint32*)sm;
    uint32* Al = Ah + 64*RS;
    uint32* Bh = Al + 64*RS;
    uint32* Bl = Bh + 64*RS;

    const int tid  = threadIdx.x;
    const int warp = tid >> 5, lane = tid & 31;
    const int g = lane >> 2, tg = lane & 3;
    const int wm = (warp & 1) * 32, wn = (warp >> 1) * 32;
    const int m0 = by * 64, n0 = bx * 64;

    // loaders: tile 64 rows x 16 k = 256 float4 slots; 2 per thread
    const int r0 = tid >> 2, q = tid & 3;
    const int r1 = r0 + 32;

    const float* gA0 = A + (size_t)(m0 + r0) * K + q * 4;
    const float* gA1 = A + (size_t)(m0 + r1) * K + q * 4;
    const float* gB0 = B + (size_t)(n0 + r0) * K + q * 4;
    const float* gB1 = B + (size_t)(n0 + r1) * K + q * 4;

    float d[2][4][4];
#pragma unroll
    for (int i = 0; i < 2; i++)
#pragma unroll
        for (int j = 0; j < 4; j++)
#pragma unroll
            for (int c = 0; c < 4; c++) d[i][j][c] = 0.f;

    const int nk = K >> 4;
    float4 pa0 = *(const float4*)(gA0);
    float4 pa1 = *(const float4*)(gA1);
    float4 pb0 = *(const float4*)(gB0);
    float4 pb1 = *(const float4*)(gB1);

    for (int t = 0; t < nk; t++) {
        split_store22(Ah, Al, r0*RS, q, pa0);
        split_store22(Ah, Al, r1*RS, q, pa1);
        split_store22(Bh, Bl, r0*RS, q, pb0);
        split_store22(Bh, Bl, r1*RS, q, pb1);
        __syncthreads();

        if (t + 1 < nk) {
            pa0 = *(const float4*)(gA0 + (t+1)*16);
            pa1 = *(const float4*)(gA1 + (t+1)*16);
            pb0 = *(const float4*)(gB0 + (t+1)*16);
            pb1 = *(const float4*)(gB1 + (t+1)*16);
        }

#pragma unroll
        for (int kf = 0; kf < 2; kf++) {
            const int pbase = kf*8 + tg*2;
            uint32 ah[2][4], al[2][4];
#pragma unroll
            for (int mf = 0; mf < 2; mf++) {
                int ra = (wm + mf*16 + g)*RS + pbase;
                int rb = ra + 8*RS;
                uint2 h0 = *(const uint2*)(Ah + ra);   // ah(k), ah(k+4) row g
                uint2 h1 = *(const uint2*)(Ah + rb);   // row g+8
                uint2 l0 = *(const uint2*)(Al + ra);
                uint2 l1 = *(const uint2*)(Al + rb);
                ah[mf][0] = h0.x; ah[mf][1] = h1.x; ah[mf][2] = h0.y; ah[mf][3] = h1.y;
                al[mf][0] = l0.x; al[mf][1] = l1.x; al[mf][2] = l0.y; al[mf][3] = l1.y;
            }
            uint32 bh[4][2], bl[4][2];
#pragma unroll
            for (int nf = 0; nf < 4; nf++) {
                int rb = (wn + nf*8 + g)*RS + pbase;
                uint2 h = *(const uint2*)(Bh + rb);
                uint2 l = *(const uint2*)(Bl + rb);
                bh[nf][0] = h.x; bh[nf][1] = h.y;
                bl[nf][0] = l.x; bl[nf][1] = l.y;
            }
#pragma unroll
            for (int mf = 0; mf < 2; mf++)
#pragma unroll
                for (int nf = 0; nf < 4; nf++) {
                    mma_tf32(d[mf][nf], ah[mf], bh[nf]);
                    mma_tf32(d[mf][nf], al[mf], bh[nf]);
                    mma_tf32(d[mf][nf], ah[mf], bl[nf]);
                }
        }
        __syncthreads();
    }

    if (!CELL) {
#pragma unroll
        for (int mf = 0; mf < 2; mf++)
#pragma unroll
            for (int nf = 0; nf < 4; nf++) {
                int r = m0 + wm + mf*16 + g;
                int c = n0 + wn + nf*8 + 2*tg;
                float b0v = bias ? bias[c]   : 0.f;
                float b1v = bias ? bias[c+1] : 0.f;
                C[(size_t)r*N + c]         = d[mf][nf][0] + b0v;
                C[(size_t)r*N + c + 1]     = d[mf][nf][1] + b1v;
                C[(size_t)(r+8)*N + c]     = d[mf][nf][2] + b0v;
                C[(size_t)(r+8)*N + c + 1] = d[mf][nf][3] + b1v;
            }
    } else {
#pragma unroll
        for (int mf = 0; mf < 2; mf++)
#pragma unroll
            for (int nf = 0; nf < 4; nf++) {
                int r = m0 + wm + mf*16 + g;
                int p = ((n0 + wn + nf*8) >> 1) + tg;
                {
                    float lr = d[mf][nf][0], li = d[mf][nf][1];
                    float mm = sqrtf(lr*lr + li*li + EPS_);
                    C[(size_t)r*TD_ + p]      = tanhf(lr / (1.f + mm));
                    C[(size_t)r*TD_ + p + D_] = tanhf(li / (1.f + mm));
                }
                {
                    float lr = d[mf][nf][2], li = d[mf][nf][3];
                    float mm = sqrtf(lr*lr + li*li + EPS_);
                    C[(size_t)(r+8)*TD_ + p]      = tanhf(lr / (1.f + mm));
                    C[(size_t)(r+8)*TD_ + p + D_] = tanhf(li / (1.f + mm));
                }
            }
    }
}

// ---------------------------------------------------------------------------
// Prep unit (545 units, 128 threads each)
// ---------------------------------------------------------------------------
__device__ void dev_prep(int b, const float* __restrict__ mag,
                         const float* __restrict__ phase,
                         const float* __restrict__ Wr, const float* __restrict__ Wi,
                         const float* __restrict__ sym, const float* __restrict__ con,
                         const int* __restrict__ x, float* sm)
{
    const int tid = threadIdx.x;

    if (b < 32) {                          // embed: 8 vocab rows
        int base = b * 8;
#pragma unroll
        for (int vv = 0; vv < 8; vv++) {
            int v = base + vv;
            for (int i = tid; i < D_; i += NTHR) {
                float r = mag[v*D_ + i];
                float t = phase[v*D_ + i];
                g_embed[v*TD_ + i]      = r * cosf(t);
                g_embed[v*TD_ + D_ + i] = r * sinf(t);
            }
        }
    } else if (b < 288) {                  // W2int: 4 rows per unit
        int idx = b - 32;
#pragma unroll
        for (int rr = 0; rr < 4; rr++) {
            int r = idx*4 + rr;
            int n = r >> 1;
            int odd = r & 1;
            for (int k = tid*4; k < TD_; k += NTHR*4) {
                float4 v;
                if (k < D_) {
                    v = *(const float4*)((odd ? Wi : Wr) + (size_t)n*D_ + k);
                } else {
                    int k2 = k - D_;
                    if (odd) v = *(const float4*)(Wr + (size_t)n*D_ + k2);
                    else {
                        v = *(const float4*)(Wi + (size_t)n*D_ + k2);
                        v.x = -v.x; v.y = -v.y; v.z = -v.z; v.w = -v.w;
                    }
                }
                *(float4*)(g_W2 + (size_t)r*TD_ + k) = v;
            }
        }
    } else if (b < 416) {                  // sym2: 4 rows per unit
        int local = b - 288;
        int w = tid >> 5, lane = tid & 31;
        int row = local*4 + w;
        float s = 0.f;
        const float* src = sym + (size_t)row*TD_;
        for (int i = lane; i < TD_; i += 32) { float v = src[i]; s += v*v; }
#pragma unroll
        for (int o = 16; o > 0; o >>= 1) s += __shfl_down_sync(0xffffffffu, s, o);
        if (lane == 0) g_sym2[row] = s;
    } else if (b < 544) {                  // conDist: 4 rows per unit
        int local = b - 416;
        int w = tid >> 5, lane = tid & 31;
        int row = local*4 + w;
        float sv[32];
#pragma unroll
        for (int c = 0; c < 32; c++) sv[c] = sym[(size_t)row*TD_ + c*32 + lane];
        float best = 1e30f;
        for (int j = 0; j < NCON_; j++) {
            const float* cj = con + (size_t)j*TD_;
            float s = 0.f;
#pragma unroll
            for (int c = 0; c < 32; c++) { float d = sv[c] - cj[c*32 + lane]; s += d*d; }
#pragma unroll
            for (int o = 16; o > 0; o >>= 1) s += __shfl_xor_sync(0xffffffffu, s, o);
            best = fminf(best, s);
        }
        if (lane == 0) g_conDist[row] = best;
    } else {                               // histogram of x
        int* hist = (int*)sm;
        hist[tid] = 0; hist[tid + 128] = 0; __syncthreads();
        for (int i = tid; i < NPOS_; i += NTHR) atomicAdd(&hist[x[i]], 1);
        __syncthreads();
        g_hist[tid] = hist[tid];
        g_hist[tid + 128] = hist[tid + 128];
        __syncthreads();
    }
}

// ---------------------------------------------------------------------------
// Trajectory (one unit = one vocab id, 128 threads)
// ---------------------------------------------------------------------------
__device__ void dev_trajectory(int v, float* sm)
{
    float* red   = sm;                  // 128
    float* sdist = sm + 128;            // 128
    int*   sidx  = (int*)(sm + 256);    // 128
    int*   memIdx= (int*)(sm + 384);    // 6
    float* wsh   = sm + 392;            // 6
    float* shconf= sm + 400;            // 1
    const int tid = threadIdx.x;

    float part = 0.f;
    for (int i = tid; i < TD_; i += NTHR) { float z = g_z0[(size_t)v*TD_ + i]; part += z*z; }
    red[tid] = part; __syncthreads();
    for (int st = 64; st > 0; st >>= 1) { if (tid < st) red[tid] += red[tid+st]; __syncthreads(); }
    float z2 = red[0];
    __syncthreads();

    float bd = 1e30f; int bi = 0;
    for (int kp = tid; kp < NSYM_; kp += NTHR) {
        float d = z2 + g_sym2[kp] - 2.f*g_Z0S[(size_t)v*NSYM_ + kp];
        if (d < bd) { bd = d; bi = kp; }
    }
    sdist[tid] = bd; sidx[tid] = bi; __syncthreads();
    for (int st = 64; st > 0; st >>= 1) {
        if (tid < st) {
            float d2 = sdist[tid+st]; int i2 = sidx[tid+st];
            if (d2 < sdist[tid] || (d2 == sdist[tid] && i2 < sidx[tid])) { sdist[tid] = d2; sidx[tid] = i2; }
        }
        __syncthreads();
    }
    int si = sidx[0]; float sd = sdist[0];
    if (tid == 0) { memIdx[0] = si; shconf[0] = 1.f/(1.f + sd); }
    float symL = sd;
    float conL = g_conDist[si];
    __syncthreads();

    for (int d = 1; d < DEPTH_; d++) {
        int k = memIdx[d-1];
        if (tid == 0) {
            float sc[DEPTH_]; float mx = -1e30f;
            float cf = shconf[0];
            for (int j = 0; j < d; j++) {
                float s = g_QK[(size_t)k*NSYM_ + memIdx[j]] * SCALE_ * cf;
                sc[j] = s; if (s > mx) mx = s;
            }
            float se = 0.f;
            for (int j = 0; j < d; j++) { sc[j] = expf(sc[j]-mx); se += sc[j]; }
            for (int j = 0; j < d; j++) wsh[j] = sc[j]/se;
        }
        __syncthreads();

        part = 0.f;
        for (int i = tid; i < TD_; i += NTHR) {
            float z = g_cellTab[(size_t)k*TD_ + i];
            for (int j = 0; j < d; j++)
                z += 0.1f * wsh[j] * g_Vsym[(size_t)memIdx[j]*TD_ + i];
            part += z*z;
        }
        red[tid] = part; __syncthreads();
        for (int st = 64; st > 0; st >>= 1) { if (tid < st) red[tid] += red[tid+st]; __syncthreads(); }
        z2 = red[0];
        __syncthreads();

        bd = 1e30f; bi = 0;
        for (int kp = tid; kp < NSYM_; kp += NTHR) {
            float zdot = g_CS[(size_t)k*NSYM_ + kp];
            for (int j = 0; j < d; j++)
                zdot += 0.1f * wsh[j] * g_VS[(size_t)memIdx[j]*NSYM_ + kp];
            float dist = z2 + g_sym2[kp] - 2.f*zdot;
            if (dist < bd) { bd = dist; bi = kp; }
        }
        sdist[tid] = bd; sidx[tid] = bi; __syncthreads();
        for (int st = 64; st > 0; st >>= 1) {
            if (tid < st) {
                float d2 = sdist[tid+st]; int i2 = sidx[tid+st];
                if (d2 < sdist[tid] || (d2 == sdist[tid] && i2 < sidx[tid])) { sdist[tid] = d2; sidx[tid] = i2; }
            }
            __syncthreads();
        }
        si = sidx[0]; sd = sdist[0];
        if (tid == 0) { memIdx[d] = si; shconf[0] = 1.f/(1.f + sd); }
        symL += sd;
        conL += g_conDist[si];
        __syncthreads();
    }

    if (tid == 0) {
        g_fin[v]   = memIdx[DEPTH_-1];
        g_symLv[v] = symL;
        g_conLv[v] = conL;
    }
    __syncthreads();
}

// ---------------------------------------------------------------------------
// Persistent mega-kernel
// ---------------------------------------------------------------------------
__global__ __launch_bounds__(NTHR, 4)
void mega_kernel(const int* __restrict__ x,
                 const float* __restrict__ mag, const float* __restrict__ phase,
                 const float* __restrict__ Wr,  const float* __restrict__ Wi,
                 const float* __restrict__ qw,  const float* __restrict__ qb,
                 const float* __restrict__ kw,  const float* __restrict__ kb,
                 const float* __restrict__ vw,  const float* __restrict__ vb,
                 const float* __restrict__ dec_w, const float* __restrict__ dec_b,
                 const float* __restrict__ sym, const float* __restrict__ con,
                 float* __restrict__ out, int writeLoss)
{
    __shared__ float sm[TGSM];
    const int b0 = blockIdx.x;

    // ---- L0: prep (545 units) ----
    for (int u = b0; u < 545; u += NBLOCKS)
        dev_prep(u, mag, phase, Wr, Wi, sym, con, x, sm);
    grid_barrier();

    // ---- L1 (384): cellTab(128) | z0(64) | Ksym(64) | Vsym(128) ----
    for (int u = b0; u < 384; u += NBLOCKS) {
        if (u < 128) {
            dev_gemm_tc<1>(sym, g_W2, nullptr, g_cellTab, TD_, TD_, u & 15, u >> 4, sm);
        } else if (u < 192) {
            int t = u - 128;
            dev_gemm_tc<1>(g_embed, g_W2, nullptr, g_z0, TD_, TD_, t & 15, t >> 4, sm);
        } else if (u < 256) {
            int t = u - 192;
            dev_gemm_tc<0>(sym, kw, kb, g_Ksym, D_, TD_, t & 7, t >> 3, sm);
        } else {
            int t = u - 256;
            dev_gemm_tc<0>(sym, vw, vb, g_Vsym, TD_, TD_, t & 15, t >> 4, sm);
        }
    }
    grid_barrier();

    // ---- L2 (352): C2(128) | Qtab(64) | CS(64) | VS(64) | Z0S(32) ----
    for (int u = b0; u < 352; u += NBLOCKS) {
        if (u < 128) {
            dev_gemm_tc<1>(g_cellTab, g_W2, nullptr, g_C2, TD_, TD_, u & 15, u >> 4, sm);
        } else if (u < 192) {
            int t = u - 128;
            dev_gemm_tc<0>(g_cellTab, qw, qb, g_Qtab, D_, TD_, t & 7, t >> 3, sm);
        } else if (u < 256) {
            int t = u - 192;
            dev_gemm_tc<0>(g_cellTab, sym, nullptr, g_CS, NSYM_, TD_, t & 7, t >> 3, sm);
        } else if (u < 320) {
            int t = u - 256;
            dev_gemm_tc<0>(g_Vsym, sym, nullptr, g_VS, NSYM_, TD_, t & 7, t >> 3, sm);
        } else {
            int t = u - 320;
            dev_gemm_tc<0>(g_z0, sym, nullptr, g_Z0S, NSYM_, TD_, t & 7, t >> 3, sm);
        }
    }
    grid_barrier();

    // ---- L3 (192): C3(128) | QK(64) ----
    for (int u = b0; u < 192; u += NBLOCKS) {
        if (u < 128) {
            dev_gemm_tc<1>(g_C2, g_W2, nullptr, g_C3, TD_, TD_, u & 15, u >> 4, sm);
        } else {
            int t = u - 128;
            dev_gemm_tc<0>(g_Qtab, g_Ksym, nullptr, g_QK, NSYM_, D_, t & 7, t >> 3, sm);
        }
    }
    grid_barrier();

    // ---- L4 (288): lookOut(32) | trajectory(256) ----
    for (int u = b0; u < 288; u += NBLOCKS) {
        if (u < 32) {
            dev_gemm_tc<0>(g_C3, dec_w, dec_b, g_lookOut, NV_, TD_, u & 3, u >> 2, sm);
        } else {
            dev_trajectory(u - 32, sm);
        }
    }
    grid_barrier();

    // ---- L5 (8193): scatter(8192) | losses(1) ----
    for (int u = b0; u < 8193; u += NBLOCKS) {
        const int tid = threadIdx.x;
        if (u < 8192) {
            int gid = u * NTHR + tid;          // 1,048,576 float4 slots
            int p = gid >> 6;
            int c = gid & 63;
            int v = __ldg(&x[p]);
            int f = g_fin[v];
            ((float4*)out)[gid] = ((const float4*)(g_lookOut + (size_t)f*NV_))[c];
        } else {
            float* red = sm;
            float h0 = (float)g_hist[tid], h1 = (float)g_hist[tid + 128];
            float s = h0 * g_symLv[tid] + h1 * g_symLv[tid + 128];
            float c = h0 * g_conLv[tid] + h1 * g_conLv[tid + 128];

            red[tid] = s; __syncthreads();
            for (int st = 64; st > 0; st >>= 1) { if (tid < st) red[tid] += red[tid+st]; __syncthreads(); }
            float st_tot = red[0]; __syncthreads();

            red[tid] = c; __syncthreads();
            for (int st = 64; st > 0; st >>= 1) { if (tid < st) red[tid] += red[tid+st]; __syncthreads(); }
            float ct_tot = red[0];

            if (tid == 0 && writeLoss) {
                float norm = (1.f + CC_) / (float)((size_t)NPOS_ * TD_);
                out[(size_t)NPOS_*NV_]     = st_tot * norm;
                out[(size_t)NPOS_*NV_ + 1] = ct_tot * norm;
            }
            __syncthreads();
        }
    }
}

// ---------------------------------------------------------------------------
// Host launcher
// ---------------------------------------------------------------------------
extern "C" void kernel_launch(void* const* d_in, const int* in_sizes, int n_in,
                              void* d_out, int out_size)
{
    const int*   x     = (const int*)d_in[0];
    const float* mag   = (const float*)d_in[1];
    const float* phase = (const float*)d_in[2];
    const float* Wr    = (const float*)d_in[3];
    const float* Wi    = (const float*)d_in[4];
    const float* qw    = (const float*)d_in[5];
    const float* qb    = (const float*)d_in[6];
    const float* kw    = (const float*)d_in[7];
    const float* kb    = (const float*)d_in[8];
    const float* vw    = (const float*)d_in[9];
    const float* vb    = (const float*)d_in[10];
    const float* dec_w = (const float*)d_in[11];
    const float* dec_b = (const float*)d_in[12];
    const float* sym   = (const float*)d_in[13];
    const float* con   = (const float*)d_in[14];
    float* out = (float*)d_out;

    int writeLoss = (out_size >= NPOS_*NV_ + 2) ? 1 : 0;

    mega_kernel<<<NBLOCKS, NTHR>>>(x, mag, phase, Wr, Wi, qw, qb, kw, kb,
                                   vw, vb, dec_w, dec_b, sym, con, out, writeLoss);
}